// round 1
// baseline (speedup 1.0000x reference)
#include <cuda_runtime.h>
#include <math.h>

#define D 128
#define SLOPE 0.2f
#define BN_EPS 1e-5f
#define MAXN 50048
#define MAXET 901120

// ---------------- scratch (static device globals: allocation-free) ----------------
__device__ __align__(16) float g_xl[MAXN * D];
__device__ __align__(16) float g_xr[MAXN * D];
__device__ __align__(16) float g_xres[MAXN * D];
__device__ __align__(16) float g_h[MAXN * D];
__device__ __align__(16) float g_x[MAXN * D];
__device__ int g_deg[MAXN];
__device__ int g_cursor[MAXN];
__device__ int g_rowptr[MAXN + 1];
__device__ int g_col[MAXET];
__device__ int g_bsum[64];
__device__ double g_dsum[D];
__device__ double g_dsq[D];
__device__ __align__(16) float g_scale[D];
__device__ __align__(16) float g_shift[D];
__device__ int g_is64;

// ---------------- edge-index dtype probe (int32 vs int64) ----------------
__global__ void k_detect(const unsigned int* __restrict__ p) {
    if (threadIdx.x == 0) {
        int is64 = 1;
        for (int i = 1; i < 256; i += 2)
            if (p[i] != 0u) { is64 = 0; break; }
        g_is64 = is64;
    }
}

// ---------------- CSR build ----------------
__global__ void k_zero_counts(int N) {
    int i = blockIdx.x * blockDim.x + threadIdx.x;
    if (i < N) { g_deg[i] = 0; g_cursor[i] = 0; }
}

__global__ void k_count(const void* __restrict__ ei, int E, int N) {
    int is64 = g_is64;
    int t = blockIdx.x * blockDim.x + threadIdx.x;
    int Et = E + N;
    if (t >= Et) return;
    int d;
    if (t < E) {
        d = is64 ? (int)((const long long*)ei)[(long long)E + t]
                 : ((const int*)ei)[E + t];
    } else {
        d = t - E;  // self loop
    }
    atomicAdd(&g_deg[d], 1);
}

__global__ void k_scan1(int N) {
    __shared__ int s[1024];
    int tid = threadIdx.x;
    int i = blockIdx.x * 1024 + tid;
    int v = (i < N) ? g_deg[i] : 0;
    s[tid] = v;
    __syncthreads();
    for (int off = 1; off < 1024; off <<= 1) {
        int t = 0;
        if (tid >= off) t = s[tid - off];
        __syncthreads();
        if (tid >= off) s[tid] += t;
        __syncthreads();
    }
    if (i < N) g_rowptr[i + 1] = s[tid];
    if (tid == 1023) g_bsum[blockIdx.x] = s[1023];
}

__global__ void k_scan2(int nb) {
    if (threadIdx.x == 0 && blockIdx.x == 0) {
        int acc = 0;
        for (int b = 0; b < nb; b++) { int v = g_bsum[b]; g_bsum[b] = acc; acc += v; }
    }
}

__global__ void k_scan3(int N) {
    int i = blockIdx.x * 1024 + threadIdx.x;
    if (i < N) g_rowptr[i + 1] += g_bsum[blockIdx.x];
    if (i == 0) g_rowptr[0] = 0;
}

__global__ void k_scatter(const void* __restrict__ ei, int E, int N) {
    int is64 = g_is64;
    int t = blockIdx.x * blockDim.x + threadIdx.x;
    int Et = E + N;
    if (t >= Et) return;
    int s, d;
    if (t < E) {
        if (is64) {
            s = (int)((const long long*)ei)[t];
            d = (int)((const long long*)ei)[(long long)E + t];
        } else {
            s = ((const int*)ei)[t];
            d = ((const int*)ei)[E + t];
        }
    } else {
        s = d = t - E;
    }
    int pos = g_rowptr[d] + atomicAdd(&g_cursor[d], 1);
    g_col[pos] = s;
}

// ---------------- SGEMM: C[M,128] = A[M,128] @ W[128,128] (+bias) ----------------
__global__ void __launch_bounds__(256, 2)
k_gemm(const float* __restrict__ A, const float* __restrict__ W,
       const float* __restrict__ bvec, float* __restrict__ C, int M) {
    __shared__ float As[16][128];
    __shared__ float Bs[16][128];
    int tid = threadIdx.x;
    int m0 = blockIdx.x * 128;
    int tx = tid & 15;       // col group
    int ty = tid >> 4;       // row group
    float acc[8][8];
#pragma unroll
    for (int i = 0; i < 8; i++)
#pragma unroll
        for (int j = 0; j < 8; j++) acc[i][j] = 0.f;

    for (int k0 = 0; k0 < 128; k0 += 16) {
        // A tile: 128 rows x 16 k, as float4 per thread (2 each)
#pragma unroll
        for (int t = tid; t < 512; t += 256) {
            int row = t >> 2;
            int kq = (t & 3) * 4;
            int gm = m0 + row;
            float4 a = make_float4(0.f, 0.f, 0.f, 0.f);
            if (gm < M) a = *(const float4*)(A + (long long)gm * 128 + k0 + kq);
            As[kq + 0][row] = a.x;
            As[kq + 1][row] = a.y;
            As[kq + 2][row] = a.z;
            As[kq + 3][row] = a.w;
        }
        // W tile: 16 k x 128 n
#pragma unroll
        for (int t = tid; t < 512; t += 256) {
            int kk = t >> 5;
            int nq = (t & 31) * 4;
            *(float4*)&Bs[kk][nq] = *(const float4*)(W + (k0 + kk) * 128 + nq);
        }
        __syncthreads();
#pragma unroll
        for (int kk = 0; kk < 16; kk++) {
            float a[8], b[8];
            float4 a0 = *(const float4*)&As[kk][ty * 8];
            float4 a1 = *(const float4*)&As[kk][ty * 8 + 4];
            float4 b0 = *(const float4*)&Bs[kk][tx * 8];
            float4 b1 = *(const float4*)&Bs[kk][tx * 8 + 4];
            a[0] = a0.x; a[1] = a0.y; a[2] = a0.z; a[3] = a0.w;
            a[4] = a1.x; a[5] = a1.y; a[6] = a1.z; a[7] = a1.w;
            b[0] = b0.x; b[1] = b0.y; b[2] = b0.z; b[3] = b0.w;
            b[4] = b1.x; b[5] = b1.y; b[6] = b1.z; b[7] = b1.w;
#pragma unroll
            for (int i = 0; i < 8; i++)
#pragma unroll
                for (int j = 0; j < 8; j++)
                    acc[i][j] = fmaf(a[i], b[j], acc[i][j]);
        }
        __syncthreads();
    }
    // epilogue
#pragma unroll
    for (int i = 0; i < 8; i++) {
        int gm = m0 + ty * 8 + i;
        if (gm >= M) continue;
#pragma unroll
        for (int j = 0; j < 8; j += 4) {
            float4 o;
            o.x = acc[i][j + 0];
            o.y = acc[i][j + 1];
            o.z = acc[i][j + 2];
            o.w = acc[i][j + 3];
            if (bvec) {
                float4 b4 = *(const float4*)(bvec + tx * 8 + j);
                o.x += b4.x; o.y += b4.y; o.z += b4.z; o.w += b4.w;
            }
            *(float4*)(C + (long long)gm * 128 + tx * 8 + j) = o;
        }
    }
}

// ---------------- fused GATv2 edge pass: score + online softmax + aggregate ----------------
// one warp per destination node; lane l owns channels [4l, 4l+4); head = lane/8
__global__ void __launch_bounds__(256)
k_gat(const float* __restrict__ xl, const float* __restrict__ xr,
      const float* __restrict__ xres, const float* __restrict__ att,
      const float* __restrict__ bias, float* __restrict__ h, int N) {
    int warp = (blockIdx.x * blockDim.x + threadIdx.x) >> 5;
    int lane = threadIdx.x & 31;
    if (warp >= N) return;
    int node = warp;

    float4 xr4 = *(const float4*)(xr + (long long)node * D + lane * 4);
    float4 a4  = *(const float4*)(att + lane * 4);

    int beg = g_rowptr[node];
    int end = g_rowptr[node + 1];

    float m = -3.0e38f, s = 0.f;
    float4 acc = make_float4(0.f, 0.f, 0.f, 0.f);

    for (int e = beg; e < end; e++) {
        int src = g_col[e];
        float4 ml = *(const float4*)(xl + (long long)src * D + lane * 4);
        float px = ml.x + xr4.x; px = px > 0.f ? px : px * SLOPE;
        float py = ml.y + xr4.y; py = py > 0.f ? py : py * SLOPE;
        float pz = ml.z + xr4.z; pz = pz > 0.f ? pz : pz * SLOPE;
        float pw = ml.w + xr4.w; pw = pw > 0.f ? pw : pw * SLOPE;
        float part = px * a4.x + py * a4.y + pz * a4.z + pw * a4.w;
        // reduce within 8-lane head group
        part += __shfl_xor_sync(0xffffffffu, part, 1);
        part += __shfl_xor_sync(0xffffffffu, part, 2);
        part += __shfl_xor_sync(0xffffffffu, part, 4);
        // online softmax (per head group)
        float mo = m;
        m = fmaxf(m, part);
        float cs = __expf(mo - m);   // 0 on first edge (exp(-inf))
        float p  = __expf(part - m);
        s = s * cs + p;
        acc.x = acc.x * cs + p * ml.x;
        acc.y = acc.y * cs + p * ml.y;
        acc.z = acc.z * cs + p * ml.z;
        acc.w = acc.w * cs + p * ml.w;
    }

    float inv = 1.f / s;  // every node has a self loop => s > 0
    float4 b4 = *(const float4*)(bias + lane * 4);
    float4 r4 = *(const float4*)(xres + (long long)node * D + lane * 4);
    float4 o;
    o.x = acc.x * inv + b4.x + r4.x;
    o.y = acc.y * inv + b4.y + r4.y;
    o.z = acc.z * inv + b4.z + r4.z;
    o.w = acc.w * inv + b4.w + r4.w;
    *(float4*)(h + (long long)node * D + lane * 4) = o;
}

// ---------------- batch norm ----------------
__global__ void k_bn_zero() {
    int t = threadIdx.x;
    if (t < D) { g_dsum[t] = 0.0; g_dsq[t] = 0.0; }
}

__global__ void k_bn_stats(const float* __restrict__ h, int N) {
    int col = threadIdx.x;   // 128 threads
    int r0 = blockIdx.x * 256;
    int r1 = r0 + 256; if (r1 > N) r1 = N;
    double s = 0.0, q = 0.0;
    for (int r = r0; r < r1; r++) {
        float v = h[(long long)r * D + col];
        s += (double)v;
        q += (double)v * (double)v;
    }
    atomicAdd(&g_dsum[col], s);
    atomicAdd(&g_dsq[col], q);
}

__global__ void k_bn_final(const float* __restrict__ gamma,
                           const float* __restrict__ beta, int N) {
    int c = threadIdx.x;
    if (c < D) {
        double mean = g_dsum[c] / (double)N;
        double var  = g_dsq[c] / (double)N - mean * mean;
        float inv = rsqrtf((float)var + BN_EPS);
        float sc = gamma[c] * inv;
        g_scale[c] = sc;
        g_shift[c] = beta[c] - (float)mean * sc;
    }
}

__global__ void k_bn_apply(const float* __restrict__ h, float* __restrict__ xo, int n4) {
    int i = blockIdx.x * blockDim.x + threadIdx.x;
    if (i >= n4) return;
    float4 v = ((const float4*)h)[i];
    int c4 = i & 31;
    float4 sc = ((const float4*)g_scale)[c4];
    float4 sh = ((const float4*)g_shift)[c4];
    v.x = fmaf(v.x, sc.x, sh.x); v.x = v.x > 0.f ? v.x : v.x * SLOPE;
    v.y = fmaf(v.y, sc.y, sh.y); v.y = v.y > 0.f ? v.y : v.y * SLOPE;
    v.z = fmaf(v.z, sc.z, sh.z); v.z = v.z > 0.f ? v.z : v.z * SLOPE;
    v.w = fmaf(v.w, sc.w, sh.w); v.w = v.w > 0.f ? v.w : v.w * SLOPE;
    ((float4*)xo)[i] = v;
}

// ---------------- launch ----------------
extern "C" void kernel_launch(void* const* d_in, const int* in_sizes, int n_in,
                              void* d_out, int out_size) {
    const float* x     = (const float*)d_in[0];
    const void*  ei    = d_in[1];
    const float* Wl    = (const float*)d_in[2];
    const float* Wr    = (const float*)d_in[3];
    const float* att   = (const float*)d_in[4];
    const float* bias  = (const float*)d_in[5];
    const float* Wres  = (const float*)d_in[6];
    const float* gamma = (const float*)d_in[7];
    const float* beta  = (const float*)d_in[8];
    const float* Wout  = (const float*)d_in[9];
    const float* bout  = (const float*)d_in[10];
    int N = in_sizes[0] / D;
    int E = in_sizes[1] / 2;
    float* out = (float*)d_out;

    float *p_xl, *p_xr, *p_xres, *p_h, *p_x;
    cudaGetSymbolAddress((void**)&p_xl, g_xl);
    cudaGetSymbolAddress((void**)&p_xr, g_xr);
    cudaGetSymbolAddress((void**)&p_xres, g_xres);
    cudaGetSymbolAddress((void**)&p_h, g_h);
    cudaGetSymbolAddress((void**)&p_x, g_x);

    int Et = E + N;
    int nb = (N + 1023) / 1024;

    k_detect<<<1, 32>>>((const unsigned int*)ei);
    k_zero_counts<<<(N + 255) / 256, 256>>>(N);
    k_count<<<(Et + 255) / 256, 256>>>(ei, E, N);
    k_scan1<<<nb, 1024>>>(N);
    k_scan2<<<1, 32>>>(nb);
    k_scan3<<<nb, 1024>>>(N);
    k_scatter<<<(Et + 255) / 256, 256>>>(ei, E, N);

    dim3 ggrid((N + 127) / 128);
    const float* xin = x;
    for (int l = 0; l < 3; l++) {
        k_gemm<<<ggrid, 256>>>(xin, Wl + l * D * D, nullptr, p_xl, N);
        k_gemm<<<ggrid, 256>>>(xin, Wr + l * D * D, nullptr, p_xr, N);
        k_gemm<<<ggrid, 256>>>(xin, Wres + l * D * D, nullptr, p_xres, N);
        k_gat<<<(N + 7) / 8, 256>>>(p_xl, p_xr, p_xres, att + l * D, bias + l * D, p_h, N);
        k_bn_zero<<<1, 128>>>();
        k_bn_stats<<<(N + 255) / 256, 128>>>(p_h, N);
        k_bn_final<<<1, 128>>>(gamma + l * D, beta + l * D, N);
        k_bn_apply<<<(N * 32 + 255) / 256, 256>>>(p_h, p_x, N * 32);
        xin = p_x;
    }
    k_gemm<<<ggrid, 256>>>(xin, Wout, bout, out, N);
}

// round 2
// speedup vs baseline: 1.0025x; 1.0025x over previous
#include <cuda_runtime.h>
#include <math.h>

#define D 128
#define SLOPE 0.2f
#define BN_EPS 1e-5f
#define MAXN 50048
#define MAXET 901120

// ---------------- scratch (static device globals: allocation-free) ----------------
__device__ __align__(16) float g_xl[MAXN * D];
__device__ __align__(16) float g_xr[MAXN * D];
__device__ __align__(16) float g_xres[MAXN * D];
__device__ __align__(16) float g_h[MAXN * D];
__device__ __align__(16) float g_x[MAXN * D];
__device__ int g_deg[MAXN];
__device__ int g_cursor[MAXN];
__device__ int g_rowptr[MAXN + 1];
__device__ int g_col[MAXET];
__device__ int g_bsum[64];
__device__ double g_dsum[D];
__device__ double g_dsq[D];
__device__ __align__(16) float g_scale[D];
__device__ __align__(16) float g_shift[D];
__device__ int g_is64;

// ---------------- edge-index dtype probe (int32 vs int64) ----------------
__global__ void k_detect(const unsigned int* __restrict__ p) {
    if (threadIdx.x == 0) {
        int is64 = 1;
        for (int i = 1; i < 256; i += 2)
            if (p[i] != 0u) { is64 = 0; break; }
        g_is64 = is64;
    }
}

// ---------------- CSR build ----------------
__global__ void k_zero_counts(int N) {
    int i = blockIdx.x * blockDim.x + threadIdx.x;
    if (i < N) { g_deg[i] = 0; g_cursor[i] = 0; }
}

__global__ void k_count(const void* __restrict__ ei, int E, int N) {
    int is64 = g_is64;
    int t = blockIdx.x * blockDim.x + threadIdx.x;
    int Et = E + N;
    if (t >= Et) return;
    int d;
    if (t < E) {
        d = is64 ? (int)((const long long*)ei)[(long long)E + t]
                 : ((const int*)ei)[E + t];
    } else {
        d = t - E;  // self loop
    }
    atomicAdd(&g_deg[d], 1);
}

__global__ void k_scan1(int N) {
    __shared__ int s[1024];
    int tid = threadIdx.x;
    int i = blockIdx.x * 1024 + tid;
    int v = (i < N) ? g_deg[i] : 0;
    s[tid] = v;
    __syncthreads();
    for (int off = 1; off < 1024; off <<= 1) {
        int t = 0;
        if (tid >= off) t = s[tid - off];
        __syncthreads();
        if (tid >= off) s[tid] += t;
        __syncthreads();
    }
    if (i < N) g_rowptr[i + 1] = s[tid];
    if (tid == 1023) g_bsum[blockIdx.x] = s[1023];
}

__global__ void k_scan2(int nb) {
    if (threadIdx.x == 0 && blockIdx.x == 0) {
        int acc = 0;
        for (int b = 0; b < nb; b++) { int v = g_bsum[b]; g_bsum[b] = acc; acc += v; }
    }
}

__global__ void k_scan3(int N) {
    int i = blockIdx.x * 1024 + threadIdx.x;
    if (i < N) g_rowptr[i + 1] += g_bsum[blockIdx.x];
    if (i == 0) g_rowptr[0] = 0;
}

__global__ void k_scatter(const void* __restrict__ ei, int E, int N) {
    int is64 = g_is64;
    int t = blockIdx.x * blockDim.x + threadIdx.x;
    int Et = E + N;
    if (t >= Et) return;
    int s, d;
    if (t < E) {
        if (is64) {
            s = (int)((const long long*)ei)[t];
            d = (int)((const long long*)ei)[(long long)E + t];
        } else {
            s = ((const int*)ei)[t];
            d = ((const int*)ei)[E + t];
        }
    } else {
        s = d = t - E;
    }
    int pos = g_rowptr[d] + atomicAdd(&g_cursor[d], 1);
    g_col[pos] = s;
}

// ---------------- SGEMM: C[M,128] = A[M,128] @ W[128,128] (+bias) ----------------
__global__ void __launch_bounds__(256, 2)
k_gemm(const float* __restrict__ A, const float* __restrict__ W,
       const float* __restrict__ bvec, float* __restrict__ C, int M) {
    __shared__ float As[16][128];
    __shared__ float Bs[16][128];
    int tid = threadIdx.x;
    int m0 = blockIdx.x * 128;
    int tx = tid & 15;       // col group
    int ty = tid >> 4;       // row group
    float acc[8][8];
#pragma unroll
    for (int i = 0; i < 8; i++)
#pragma unroll
        for (int j = 0; j < 8; j++) acc[i][j] = 0.f;

    for (int k0 = 0; k0 < 128; k0 += 16) {
        // A tile: 128 rows x 16 k, as float4 per thread (2 each)
#pragma unroll
        for (int t = tid; t < 512; t += 256) {
            int row = t >> 2;
            int kq = (t & 3) * 4;
            int gm = m0 + row;
            float4 a = make_float4(0.f, 0.f, 0.f, 0.f);
            if (gm < M) a = *(const float4*)(A + (long long)gm * 128 + k0 + kq);
            As[kq + 0][row] = a.x;
            As[kq + 1][row] = a.y;
            As[kq + 2][row] = a.z;
            As[kq + 3][row] = a.w;
        }
        // W tile: 16 k x 128 n
#pragma unroll
        for (int t = tid; t < 512; t += 256) {
            int kk = t >> 5;
            int nq = (t & 31) * 4;
            *(float4*)&Bs[kk][nq] = *(const float4*)(W + (k0 + kk) * 128 + nq);
        }
        __syncthreads();
#pragma unroll
        for (int kk = 0; kk < 16; kk++) {
            float a[8], b[8];
            float4 a0 = *(const float4*)&As[kk][ty * 8];
            float4 a1 = *(const float4*)&As[kk][ty * 8 + 4];
            float4 b0 = *(const float4*)&Bs[kk][tx * 8];
            float4 b1 = *(const float4*)&Bs[kk][tx * 8 + 4];
            a[0] = a0.x; a[1] = a0.y; a[2] = a0.z; a[3] = a0.w;
            a[4] = a1.x; a[5] = a1.y; a[6] = a1.z; a[7] = a1.w;
            b[0] = b0.x; b[1] = b0.y; b[2] = b0.z; b[3] = b0.w;
            b[4] = b1.x; b[5] = b1.y; b[6] = b1.z; b[7] = b1.w;
#pragma unroll
            for (int i = 0; i < 8; i++)
#pragma unroll
                for (int j = 0; j < 8; j++)
                    acc[i][j] = fmaf(a[i], b[j], acc[i][j]);
        }
        __syncthreads();
    }
    // epilogue
#pragma unroll
    for (int i = 0; i < 8; i++) {
        int gm = m0 + ty * 8 + i;
        if (gm >= M) continue;
#pragma unroll
        for (int j = 0; j < 8; j += 4) {
            float4 o;
            o.x = acc[i][j + 0];
            o.y = acc[i][j + 1];
            o.z = acc[i][j + 2];
            o.w = acc[i][j + 3];
            if (bvec) {
                float4 b4 = *(const float4*)(bvec + tx * 8 + j);
                o.x += b4.x; o.y += b4.y; o.z += b4.z; o.w += b4.w;
            }
            *(float4*)(C + (long long)gm * 128 + tx * 8 + j) = o;
        }
    }
}

// ---------------- fused GATv2 edge pass: score + online softmax + aggregate ----------------
// one warp per destination node; lane l owns channels [4l, 4l+4); head = lane/8
__global__ void __launch_bounds__(256)
k_gat(const float* __restrict__ xl, const float* __restrict__ xr,
      const float* __restrict__ xres, const float* __restrict__ att,
      const float* __restrict__ bias, float* __restrict__ h, int N) {
    int warp = (blockIdx.x * blockDim.x + threadIdx.x) >> 5;
    int lane = threadIdx.x & 31;
    if (warp >= N) return;
    int node = warp;

    float4 xr4 = *(const float4*)(xr + (long long)node * D + lane * 4);
    float4 a4  = *(const float4*)(att + lane * 4);

    int beg = g_rowptr[node];
    int end = g_rowptr[node + 1];

    float m = -3.0e38f, s = 0.f;
    float4 acc = make_float4(0.f, 0.f, 0.f, 0.f);

    for (int e = beg; e < end; e++) {
        int src = g_col[e];
        float4 ml = *(const float4*)(xl + (long long)src * D + lane * 4);
        float px = ml.x + xr4.x; px = px > 0.f ? px : px * SLOPE;
        float py = ml.y + xr4.y; py = py > 0.f ? py : py * SLOPE;
        float pz = ml.z + xr4.z; pz = pz > 0.f ? pz : pz * SLOPE;
        float pw = ml.w + xr4.w; pw = pw > 0.f ? pw : pw * SLOPE;
        float part = px * a4.x + py * a4.y + pz * a4.z + pw * a4.w;
        // reduce within 8-lane head group
        part += __shfl_xor_sync(0xffffffffu, part, 1);
        part += __shfl_xor_sync(0xffffffffu, part, 2);
        part += __shfl_xor_sync(0xffffffffu, part, 4);
        // online softmax (per head group)
        float mo = m;
        m = fmaxf(m, part);
        float cs = __expf(mo - m);   // 0 on first edge (exp(-inf))
        float p  = __expf(part - m);
        s = s * cs + p;
        acc.x = acc.x * cs + p * ml.x;
        acc.y = acc.y * cs + p * ml.y;
        acc.z = acc.z * cs + p * ml.z;
        acc.w = acc.w * cs + p * ml.w;
    }

    float inv = 1.f / s;  // every node has a self loop => s > 0
    float4 b4 = *(const float4*)(bias + lane * 4);
    float4 r4 = *(const float4*)(xres + (long long)node * D + lane * 4);
    float4 o;
    o.x = acc.x * inv + b4.x + r4.x;
    o.y = acc.y * inv + b4.y + r4.y;
    o.z = acc.z * inv + b4.z + r4.z;
    o.w = acc.w * inv + b4.w + r4.w;
    *(float4*)(h + (long long)node * D + lane * 4) = o;
}

// ---------------- batch norm ----------------
__global__ void k_bn_zero() {
    int t = threadIdx.x;
    if (t < D) { g_dsum[t] = 0.0; g_dsq[t] = 0.0; }
}

__global__ void k_bn_stats(const float* __restrict__ h, int N) {
    int col = threadIdx.x;   // 128 threads
    int r0 = blockIdx.x * 256;
    int r1 = r0 + 256; if (r1 > N) r1 = N;
    double s = 0.0, q = 0.0;
    for (int r = r0; r < r1; r++) {
        float v = h[(long long)r * D + col];
        s += (double)v;
        q += (double)v * (double)v;
    }
    atomicAdd(&g_dsum[col], s);
    atomicAdd(&g_dsq[col], q);
}

__global__ void k_bn_final(const float* __restrict__ gamma,
                           const float* __restrict__ beta, int N) {
    int c = threadIdx.x;
    if (c < D) {
        double mean = g_dsum[c] / (double)N;
        double var  = g_dsq[c] / (double)N - mean * mean;
        float inv = rsqrtf((float)var + BN_EPS);
        float sc = gamma[c] * inv;
        g_scale[c] = sc;
        g_shift[c] = beta[c] - (float)mean * sc;
    }
}

__global__ void k_bn_apply(const float* __restrict__ h, float* __restrict__ xo, int n4) {
    int i = blockIdx.x * blockDim.x + threadIdx.x;
    if (i >= n4) return;
    float4 v = ((const float4*)h)[i];
    int c4 = i & 31;
    float4 sc = ((const float4*)g_scale)[c4];
    float4 sh = ((const float4*)g_shift)[c4];
    v.x = fmaf(v.x, sc.x, sh.x); v.x = v.x > 0.f ? v.x : v.x * SLOPE;
    v.y = fmaf(v.y, sc.y, sh.y); v.y = v.y > 0.f ? v.y : v.y * SLOPE;
    v.z = fmaf(v.z, sc.z, sh.z); v.z = v.z > 0.f ? v.z : v.z * SLOPE;
    v.w = fmaf(v.w, sc.w, sh.w); v.w = v.w > 0.f ? v.w : v.w * SLOPE;
    ((float4*)xo)[i] = v;
}

// ---------------- launch ----------------
extern "C" void kernel_launch(void* const* d_in, const int* in_sizes, int n_in,
                              void* d_out, int out_size) {
    const float* x     = (const float*)d_in[0];
    const void*  ei    = d_in[1];
    const float* Wl    = (const float*)d_in[2];
    const float* Wr    = (const float*)d_in[3];
    const float* att   = (const float*)d_in[4];
    const float* bias  = (const float*)d_in[5];
    const float* Wres  = (const float*)d_in[6];
    const float* gamma = (const float*)d_in[7];
    const float* beta  = (const float*)d_in[8];
    const float* Wout  = (const float*)d_in[9];
    const float* bout  = (const float*)d_in[10];
    int N = in_sizes[0] / D;
    int E = in_sizes[1] / 2;
    float* out = (float*)d_out;

    float *p_xl, *p_xr, *p_xres, *p_h, *p_x;
    cudaGetSymbolAddress((void**)&p_xl, g_xl);
    cudaGetSymbolAddress((void**)&p_xr, g_xr);
    cudaGetSymbolAddress((void**)&p_xres, g_xres);
    cudaGetSymbolAddress((void**)&p_h, g_h);
    cudaGetSymbolAddress((void**)&p_x, g_x);

    int Et = E + N;
    int nb = (N + 1023) / 1024;

    k_detect<<<1, 32>>>((const unsigned int*)ei);
    k_zero_counts<<<(N + 255) / 256, 256>>>(N);
    k_count<<<(Et + 255) / 256, 256>>>(ei, E, N);
    k_scan1<<<nb, 1024>>>(N);
    k_scan2<<<1, 32>>>(nb);
    k_scan3<<<nb, 1024>>>(N);
    k_scatter<<<(Et + 255) / 256, 256>>>(ei, E, N);

    dim3 ggrid((N + 127) / 128);
    const float* xin = x;
    for (int l = 0; l < 3; l++) {
        k_gemm<<<ggrid, 256>>>(xin, Wl + l * D * D, nullptr, p_xl, N);
        k_gemm<<<ggrid, 256>>>(xin, Wr + l * D * D, nullptr, p_xr, N);
        k_gemm<<<ggrid, 256>>>(xin, Wres + l * D * D, nullptr, p_xres, N);
        k_gat<<<(N + 7) / 8, 256>>>(p_xl, p_xr, p_xres, att + l * D, bias + l * D, p_h, N);
        k_bn_zero<<<1, 128>>>();
        k_bn_stats<<<(N + 255) / 256, 128>>>(p_h, N);
        k_bn_final<<<1, 128>>>(gamma + l * D, beta + l * D, N);
        k_bn_apply<<<(N * 32 + 255) / 256, 256>>>(p_h, p_x, N * 32);
        xin = p_x;
    }
    k_gemm<<<ggrid, 256>>>(xin, Wout, bout, out, N);
}

// round 3
// speedup vs baseline: 1.6603x; 1.6561x over previous
#include <cuda_runtime.h>
#include <math.h>

#define D 128
#define SLOPE 0.2f
#define BN_EPS 1e-5f
#define MAXN 50048
#define MAXET 901120

// ---------------- scratch (static device globals: allocation-free) ----------------
__device__ __align__(16) float g_xl[MAXN * D];
__device__ __align__(16) float g_xr[MAXN * D];
__device__ __align__(16) float g_xres[MAXN * D];
__device__ __align__(16) float g_h[MAXN * D];
__device__ int g_deg[MAXN];
__device__ int g_cursor[MAXN];
__device__ int g_rowptr[MAXN + 1];
__device__ int g_col[MAXET];
__device__ int g_bsum[64];
__device__ double g_dsum[D];
__device__ double g_dsq[D];
__device__ __align__(16) float g_scale[D];
__device__ __align__(16) float g_shift[D];
__device__ int g_is64;

// ---------------- edge-index dtype probe (int32 vs int64) ----------------
__global__ void k_detect(const unsigned int* __restrict__ p) {
    if (threadIdx.x == 0) {
        int is64 = 1;
        for (int i = 1; i < 256; i += 2)
            if (p[i] != 0u) { is64 = 0; break; }
        g_is64 = is64;
    }
}

// ---------------- CSR build ----------------
__global__ void k_zero_counts(int N) {
    int i = blockIdx.x * blockDim.x + threadIdx.x;
    if (i < N) { g_deg[i] = 0; g_cursor[i] = 0; }
}

__global__ void k_count(const void* __restrict__ ei, int E, int N) {
    int is64 = g_is64;
    int t = blockIdx.x * blockDim.x + threadIdx.x;
    int Et = E + N;
    if (t >= Et) return;
    int d;
    if (t < E) {
        d = is64 ? (int)((const long long*)ei)[(long long)E + t]
                 : ((const int*)ei)[E + t];
    } else {
        d = t - E;  // self loop
    }
    atomicAdd(&g_deg[d], 1);
}

__global__ void k_scan1(int N) {
    __shared__ int s[1024];
    int tid = threadIdx.x;
    int i = blockIdx.x * 1024 + tid;
    int v = (i < N) ? g_deg[i] : 0;
    s[tid] = v;
    __syncthreads();
    for (int off = 1; off < 1024; off <<= 1) {
        int t = 0;
        if (tid >= off) t = s[tid - off];
        __syncthreads();
        if (tid >= off) s[tid] += t;
        __syncthreads();
    }
    if (i < N) g_rowptr[i + 1] = s[tid];
    if (tid == 1023) g_bsum[blockIdx.x] = s[1023];
}

__global__ void k_scan2(int nb) {
    if (threadIdx.x == 0 && blockIdx.x == 0) {
        int acc = 0;
        for (int b = 0; b < nb; b++) { int v = g_bsum[b]; g_bsum[b] = acc; acc += v; }
    }
}

__global__ void k_scan3(int N) {
    int i = blockIdx.x * 1024 + threadIdx.x;
    if (i < N) g_rowptr[i + 1] += g_bsum[blockIdx.x];
    if (i == 0) g_rowptr[0] = 0;
}

__global__ void k_scatter(const void* __restrict__ ei, int E, int N) {
    int is64 = g_is64;
    int t = blockIdx.x * blockDim.x + threadIdx.x;
    int Et = E + N;
    if (t >= Et) return;
    int s, d;
    if (t < E) {
        if (is64) {
            s = (int)((const long long*)ei)[t];
            d = (int)((const long long*)ei)[(long long)E + t];
        } else {
            s = ((const int*)ei)[t];
            d = ((const int*)ei)[E + t];
        }
    } else {
        s = d = t - E;
    }
    int pos = g_rowptr[d] + atomicAdd(&g_cursor[d], 1);
    g_col[pos] = s;
}

// ---------------- tf32 tensor-core GEMM ----------------
// C[M,128] = act(A)[M,128] @ W[128,128] (+bias)
// act = identity (affine==0) or per-column BN affine + leaky-relu (affine==1)
// Block: 256 threads (8 warps, 4x2), C tile 128x128, warp tile 32x64.
__device__ __forceinline__ unsigned f2tf(float x) {
    unsigned r;
    asm("cvt.rna.tf32.f32 %0, %1;" : "=r"(r) : "f"(x));
    return r;
}

__global__ void __launch_bounds__(256, 2)
k_gemm3(const float* __restrict__ A,
        const float* __restrict__ W0, const float* __restrict__ W1,
        const float* __restrict__ W2,
        float* __restrict__ C0, float* __restrict__ C1, float* __restrict__ C2,
        const float* __restrict__ bvec, int M, int affine) {
    const float* W = (blockIdx.y == 0) ? W0 : (blockIdx.y == 1 ? W1 : W2);
    float* C = (blockIdx.y == 0) ? C0 : (blockIdx.y == 1 ? C1 : C2);

    __shared__ unsigned As[128][36];   // padded: bank = 4r+c (conflict-free frags)
    __shared__ unsigned Ws[32][132];

    int tid = threadIdx.x;
    int warp = tid >> 5;
    int lane = tid & 31;
    int wm = warp >> 1;           // 0..3  -> 32-row slab
    int wn = warp & 1;            // 0..1  -> 64-col slab
    int m0 = blockIdx.x * 128;

    int qr = lane >> 2;           // 0..7
    int qc = lane & 3;            // 0..3

    float acc[2][8][4];
#pragma unroll
    for (int i = 0; i < 2; i++)
#pragma unroll
        for (int j = 0; j < 8; j++)
#pragma unroll
            for (int k = 0; k < 4; k++) acc[i][j][k] = 0.f;

    int arow = tid >> 3;          // 0..31
    int acol = (tid & 7) * 4;     // 0..28
    int wrow = tid >> 5;          // 0..7
    int wcol = (tid & 31) * 4;    // 0..124

    for (int k0 = 0; k0 < 128; k0 += 32) {
        // A chunk 128x32
#pragma unroll
        for (int rr = 0; rr < 128; rr += 32) {
            int gm = m0 + arow + rr;
            float4 v = make_float4(0.f, 0.f, 0.f, 0.f);
            if (gm < M) v = *(const float4*)(A + (long long)gm * 128 + k0 + acol);
            if (affine) {
                float4 sc = *(const float4*)(g_scale + k0 + acol);
                float4 sh = *(const float4*)(g_shift + k0 + acol);
                v.x = fmaf(v.x, sc.x, sh.x); v.x = v.x > 0.f ? v.x : v.x * SLOPE;
                v.y = fmaf(v.y, sc.y, sh.y); v.y = v.y > 0.f ? v.y : v.y * SLOPE;
                v.z = fmaf(v.z, sc.z, sh.z); v.z = v.z > 0.f ? v.z : v.z * SLOPE;
                v.w = fmaf(v.w, sc.w, sh.w); v.w = v.w > 0.f ? v.w : v.w * SLOPE;
            }
            As[arow + rr][acol + 0] = f2tf(v.x);
            As[arow + rr][acol + 1] = f2tf(v.y);
            As[arow + rr][acol + 2] = f2tf(v.z);
            As[arow + rr][acol + 3] = f2tf(v.w);
        }
        // W chunk 32x128
#pragma unroll
        for (int kk = wrow; kk < 32; kk += 8) {
            float4 w = *(const float4*)(W + (k0 + kk) * 128 + wcol);
            Ws[kk][wcol + 0] = f2tf(w.x);
            Ws[kk][wcol + 1] = f2tf(w.y);
            Ws[kk][wcol + 2] = f2tf(w.z);
            Ws[kk][wcol + 3] = f2tf(w.w);
        }
        __syncthreads();

#pragma unroll
        for (int ks = 0; ks < 4; ks++) {
            int kb = ks * 8;
            unsigned a[2][4];
#pragma unroll
            for (int mi = 0; mi < 2; mi++) {
                int rb = wm * 32 + mi * 16 + qr;
                a[mi][0] = As[rb][kb + qc];
                a[mi][1] = As[rb + 8][kb + qc];
                a[mi][2] = As[rb][kb + qc + 4];
                a[mi][3] = As[rb + 8][kb + qc + 4];
            }
#pragma unroll
            for (int ni = 0; ni < 8; ni++) {
                int n = wn * 64 + ni * 8 + qr;
                unsigned b0 = Ws[kb + qc][n];
                unsigned b1 = Ws[kb + qc + 4][n];
#pragma unroll
                for (int mi = 0; mi < 2; mi++) {
                    asm volatile(
                        "mma.sync.aligned.m16n8k8.row.col.f32.tf32.tf32.f32 "
                        "{%0,%1,%2,%3}, {%4,%5,%6,%7}, {%8,%9}, {%0,%1,%2,%3};\n"
                        : "+f"(acc[mi][ni][0]), "+f"(acc[mi][ni][1]),
                          "+f"(acc[mi][ni][2]), "+f"(acc[mi][ni][3])
                        : "r"(a[mi][0]), "r"(a[mi][1]), "r"(a[mi][2]), "r"(a[mi][3]),
                          "r"(b0), "r"(b1));
                }
            }
        }
        __syncthreads();
    }

    // epilogue
#pragma unroll
    for (int mi = 0; mi < 2; mi++) {
        int r0 = m0 + wm * 32 + mi * 16 + qr;
#pragma unroll
        for (int ni = 0; ni < 8; ni++) {
            int col = wn * 64 + ni * 8 + qc * 2;
            float bx = 0.f, by = 0.f;
            if (bvec) { bx = bvec[col]; by = bvec[col + 1]; }
            if (r0 < M) {
                float2 o; o.x = acc[mi][ni][0] + bx; o.y = acc[mi][ni][1] + by;
                *(float2*)(C + (long long)r0 * 128 + col) = o;
            }
            if (r0 + 8 < M) {
                float2 o; o.x = acc[mi][ni][2] + bx; o.y = acc[mi][ni][3] + by;
                *(float2*)(C + (long long)(r0 + 8) * 128 + col) = o;
            }
        }
    }
}

// ---------------- fused GATv2 edge pass: score + online softmax + aggregate ----------------
// one warp per destination node; lane l owns channels [4l, 4l+4); head = lane/8
#define GAT_STEP(ML)                                                        \
    {                                                                       \
        float px = (ML).x + xr4.x; px = px > 0.f ? px : px * SLOPE;         \
        float py = (ML).y + xr4.y; py = py > 0.f ? py : py * SLOPE;         \
        float pz = (ML).z + xr4.z; pz = pz > 0.f ? pz : pz * SLOPE;         \
        float pw = (ML).w + xr4.w; pw = pw > 0.f ? pw : pw * SLOPE;         \
        float part = px * a4.x + py * a4.y + pz * a4.z + pw * a4.w;         \
        part += __shfl_xor_sync(0xffffffffu, part, 1);                      \
        part += __shfl_xor_sync(0xffffffffu, part, 2);                      \
        part += __shfl_xor_sync(0xffffffffu, part, 4);                      \
        float mo = m;                                                       \
        m = fmaxf(m, part);                                                 \
        float cs = __expf(mo - m);                                          \
        float p  = __expf(part - m);                                        \
        s = s * cs + p;                                                     \
        acc.x = acc.x * cs + p * (ML).x;                                    \
        acc.y = acc.y * cs + p * (ML).y;                                    \
        acc.z = acc.z * cs + p * (ML).z;                                    \
        acc.w = acc.w * cs + p * (ML).w;                                    \
    }

__global__ void __launch_bounds__(256)
k_gat(const float* __restrict__ xl, const float* __restrict__ xr,
      const float* __restrict__ xres, const float* __restrict__ att,
      const float* __restrict__ bias, float* __restrict__ h, int N) {
    int warp = (blockIdx.x * blockDim.x + threadIdx.x) >> 5;
    int lane = threadIdx.x & 31;
    if (warp >= N) return;
    int node = warp;

    float4 xr4 = *(const float4*)(xr + (long long)node * D + lane * 4);
    float4 a4  = *(const float4*)(att + lane * 4);

    int beg = g_rowptr[node];
    int end = g_rowptr[node + 1];

    float m = -3.0e38f, s = 0.f;
    float4 acc = make_float4(0.f, 0.f, 0.f, 0.f);

    int e = beg;
    for (; e + 2 <= end; e += 2) {
        int s0 = g_col[e];
        int s1 = g_col[e + 1];
        float4 ml0 = *(const float4*)(xl + (long long)s0 * D + lane * 4);
        float4 ml1 = *(const float4*)(xl + (long long)s1 * D + lane * 4);
        GAT_STEP(ml0);
        GAT_STEP(ml1);
    }
    if (e < end) {
        int s0 = g_col[e];
        float4 ml0 = *(const float4*)(xl + (long long)s0 * D + lane * 4);
        GAT_STEP(ml0);
    }

    float inv = 1.f / s;  // every node has a self loop => s > 0
    float4 b4 = *(const float4*)(bias + lane * 4);
    float4 r4 = *(const float4*)(xres + (long long)node * D + lane * 4);
    float4 o;
    o.x = acc.x * inv + b4.x + r4.x;
    o.y = acc.y * inv + b4.y + r4.y;
    o.z = acc.z * inv + b4.z + r4.z;
    o.w = acc.w * inv + b4.w + r4.w;
    *(float4*)(h + (long long)node * D + lane * 4) = o;
}

// ---------------- batch norm ----------------
__global__ void k_bn_zero() {
    int t = threadIdx.x;
    if (t < D) { g_dsum[t] = 0.0; g_dsq[t] = 0.0; }
}

__global__ void k_bn_stats(const float* __restrict__ h, int N) {
    int col = threadIdx.x;   // 128 threads
    int r0 = blockIdx.x * 256;
    int r1 = r0 + 256; if (r1 > N) r1 = N;
    double s = 0.0, q = 0.0;
    for (int r = r0; r < r1; r++) {
        float v = h[(long long)r * D + col];
        s += (double)v;
        q += (double)v * (double)v;
    }
    atomicAdd(&g_dsum[col], s);
    atomicAdd(&g_dsq[col], q);
}

__global__ void k_bn_final(const float* __restrict__ gamma,
                           const float* __restrict__ beta, int N) {
    int c = threadIdx.x;
    if (c < D) {
        double mean = g_dsum[c] / (double)N;
        double var  = g_dsq[c] / (double)N - mean * mean;
        float inv = rsqrtf((float)var + BN_EPS);
        float sc = gamma[c] * inv;
        g_scale[c] = sc;
        g_shift[c] = beta[c] - (float)mean * sc;
    }
}

// ---------------- launch ----------------
extern "C" void kernel_launch(void* const* d_in, const int* in_sizes, int n_in,
                              void* d_out, int out_size) {
    const float* x     = (const float*)d_in[0];
    const void*  ei    = d_in[1];
    const float* Wl    = (const float*)d_in[2];
    const float* Wr    = (const float*)d_in[3];
    const float* att   = (const float*)d_in[4];
    const float* bias  = (const float*)d_in[5];
    const float* Wres  = (const float*)d_in[6];
    const float* gamma = (const float*)d_in[7];
    const float* beta  = (const float*)d_in[8];
    const float* Wout  = (const float*)d_in[9];
    const float* bout  = (const float*)d_in[10];
    int N = in_sizes[0] / D;
    int E = in_sizes[1] / 2;
    float* out = (float*)d_out;

    float *p_xl, *p_xr, *p_xres, *p_h;
    cudaGetSymbolAddress((void**)&p_xl, g_xl);
    cudaGetSymbolAddress((void**)&p_xr, g_xr);
    cudaGetSymbolAddress((void**)&p_xres, g_xres);
    cudaGetSymbolAddress((void**)&p_h, g_h);

    int Et = E + N;
    int nb = (N + 1023) / 1024;

    k_detect<<<1, 32>>>((const unsigned int*)ei);
    k_zero_counts<<<(N + 255) / 256, 256>>>(N);
    k_count<<<(Et + 255) / 256, 256>>>(ei, E, N);
    k_scan1<<<nb, 1024>>>(N);
    k_scan2<<<1, 32>>>(nb);
    k_scan3<<<nb, 1024>>>(N);
    k_scatter<<<(Et + 255) / 256, 256>>>(ei, E, N);

    int mtiles = (N + 127) / 128;
    dim3 g3(mtiles, 3);
    dim3 g1(mtiles, 1);

    const float* xin = x;
    for (int l = 0; l < 3; l++) {
        int affine = (l > 0) ? 1 : 0;
        k_gemm3<<<g3, 256>>>(xin,
                             Wl + l * D * D, Wr + l * D * D, Wres + l * D * D,
                             p_xl, p_xr, p_xres, nullptr, N, affine);
        k_gat<<<(N + 7) / 8, 256>>>(p_xl, p_xr, p_xres, att + l * D, bias + l * D, p_h, N);
        k_bn_zero<<<1, 128>>>();
        k_bn_stats<<<(N + 255) / 256, 128>>>(p_h, N);
        k_bn_final<<<1, 128>>>(gamma + l * D, beta + l * D, N);
        xin = p_h;
    }
    k_gemm3<<<g1, 256>>>(p_h, Wout, Wout, Wout, out, out, out, bout, N, 1);
}

// round 4
// speedup vs baseline: 1.8950x; 1.1414x over previous
#include <cuda_runtime.h>
#include <math.h>

#define D 128
#define SLOPE 0.2f
#define BN_EPS 1e-5f
#define MAXN 50048
#define MAXET 901120

// ---------------- scratch (static device globals: allocation-free) ----------------
__device__ __align__(16) float g_xl[MAXN * D];
__device__ __align__(16) float g_xr[MAXN * D];
__device__ __align__(16) float g_xres[MAXN * D];
__device__ __align__(16) float g_h[MAXN * D];
__device__ int g_deg[MAXN];
__device__ int g_cursor[MAXN];
__device__ int g_rowptr[MAXN + 1];
__device__ int g_col[MAXET];
__device__ int g_bsum[64];
__device__ double g_dsum[D];
__device__ double g_dsq[D];
__device__ __align__(16) float g_scale[D];
__device__ __align__(16) float g_shift[D];
__device__ int g_is64;
__device__ int g_ticket;

// ---------------- init: zero counts + edge dtype probe ----------------
__global__ void k_init(const unsigned int* __restrict__ p, int N) {
    int i = blockIdx.x * blockDim.x + threadIdx.x;
    if (i < N) { g_deg[i] = 0; g_cursor[i] = 0; }
    if (i == 0) {
        int is64 = 1;
        for (int j = 1; j < 256; j += 2)
            if (p[j] != 0u) { is64 = 0; break; }
        g_is64 = is64;
    }
}

// ---------------- CSR build ----------------
__global__ void k_count(const void* __restrict__ ei, int E, int N) {
    int is64 = g_is64;
    int t = blockIdx.x * blockDim.x + threadIdx.x;
    int Et = E + N;
    if (t >= Et) return;
    int d;
    if (t < E) {
        d = is64 ? (int)((const long long*)ei)[(long long)E + t]
                 : ((const int*)ei)[E + t];
    } else {
        d = t - E;  // self loop
    }
    atomicAdd(&g_deg[d], 1);
}

__global__ void k_scan1(int N) {
    __shared__ int s[1024];
    int tid = threadIdx.x;
    int i = blockIdx.x * 1024 + tid;
    int v = (i < N) ? g_deg[i] : 0;
    s[tid] = v;
    __syncthreads();
    for (int off = 1; off < 1024; off <<= 1) {
        int t = 0;
        if (tid >= off) t = s[tid - off];
        __syncthreads();
        if (tid >= off) s[tid] += t;
        __syncthreads();
    }
    if (i < N) g_rowptr[i + 1] = s[tid];
    if (tid == 1023) g_bsum[blockIdx.x] = s[1023];
}

// scan of block totals done inline per block (<=49 iters), then add
__global__ void k_scan3(int N) {
    __shared__ int sbase;
    if (threadIdx.x == 0) {
        int acc = 0;
        for (int b = 0; b < blockIdx.x; b++) acc += g_bsum[b];
        sbase = acc;
    }
    __syncthreads();
    int i = blockIdx.x * 1024 + threadIdx.x;
    if (i < N) g_rowptr[i + 1] += sbase;
    if (i == 0) g_rowptr[0] = 0;
}

__global__ void k_scatter(const void* __restrict__ ei, int E, int N) {
    int is64 = g_is64;
    int t = blockIdx.x * blockDim.x + threadIdx.x;
    int Et = E + N;
    if (t >= Et) return;
    int s, d;
    if (t < E) {
        if (is64) {
            s = (int)((const long long*)ei)[t];
            d = (int)((const long long*)ei)[(long long)E + t];
        } else {
            s = ((const int*)ei)[t];
            d = ((const int*)ei)[E + t];
        }
    } else {
        s = d = t - E;
    }
    int pos = g_rowptr[d] + atomicAdd(&g_cursor[d], 1);
    g_col[pos] = s;
}

// ---------------- tf32 tensor-core GEMM ----------------
// C[M,128] = act(A)[M,128] @ W[128,128] (+bias)
// act = identity (affine==0) or per-column BN affine + leaky-relu (affine==1)
// Block: 256 threads (8 warps, 4x2), C tile 128x128, warp tile 32x64.
// Block (0,0) also zeroes the BN accumulators for the following k_gat_bn.
__device__ __forceinline__ unsigned f2tf(float x) {
    unsigned r;
    asm("cvt.rna.tf32.f32 %0, %1;" : "=r"(r) : "f"(x));
    return r;
}

__global__ void __launch_bounds__(256, 2)
k_gemm3(const float* __restrict__ A,
        const float* __restrict__ W0, const float* __restrict__ W1,
        const float* __restrict__ W2,
        float* __restrict__ C0, float* __restrict__ C1, float* __restrict__ C2,
        const float* __restrict__ bvec, int M, int affine) {
    const float* W = (blockIdx.y == 0) ? W0 : (blockIdx.y == 1 ? W1 : W2);
    float* C = (blockIdx.y == 0) ? C0 : (blockIdx.y == 1 ? C1 : C2);

    __shared__ unsigned As[128][36];   // padded: bank = 4r+c (conflict-free frags)
    __shared__ unsigned Ws[32][132];

    int tid = threadIdx.x;
    int warp = tid >> 5;
    int lane = tid & 31;

    // zero BN accumulators for the following fused GAT+BN kernel
    if (blockIdx.x == 0 && blockIdx.y == 0) {
        if (tid < 128) { g_dsum[tid] = 0.0; g_dsq[tid] = 0.0; }
        if (tid == 0) g_ticket = 0;
    }

    int wm = warp >> 1;           // 0..3  -> 32-row slab
    int wn = warp & 1;            // 0..1  -> 64-col slab
    int m0 = blockIdx.x * 128;

    int qr = lane >> 2;           // 0..7
    int qc = lane & 3;            // 0..3

    float acc[2][8][4];
#pragma unroll
    for (int i = 0; i < 2; i++)
#pragma unroll
        for (int j = 0; j < 8; j++)
#pragma unroll
            for (int k = 0; k < 4; k++) acc[i][j][k] = 0.f;

    int arow = tid >> 3;          // 0..31
    int acol = (tid & 7) * 4;     // 0..28
    int wrow = tid >> 5;          // 0..7
    int wcol = (tid & 31) * 4;    // 0..124

    for (int k0 = 0; k0 < 128; k0 += 32) {
        // A chunk 128x32
#pragma unroll
        for (int rr = 0; rr < 128; rr += 32) {
            int gm = m0 + arow + rr;
            float4 v = make_float4(0.f, 0.f, 0.f, 0.f);
            if (gm < M) v = *(const float4*)(A + (long long)gm * 128 + k0 + acol);
            if (affine) {
                float4 sc = *(const float4*)(g_scale + k0 + acol);
                float4 sh = *(const float4*)(g_shift + k0 + acol);
                v.x = fmaf(v.x, sc.x, sh.x); v.x = v.x > 0.f ? v.x : v.x * SLOPE;
                v.y = fmaf(v.y, sc.y, sh.y); v.y = v.y > 0.f ? v.y : v.y * SLOPE;
                v.z = fmaf(v.z, sc.z, sh.z); v.z = v.z > 0.f ? v.z : v.z * SLOPE;
                v.w = fmaf(v.w, sc.w, sh.w); v.w = v.w > 0.f ? v.w : v.w * SLOPE;
            }
            As[arow + rr][acol + 0] = f2tf(v.x);
            As[arow + rr][acol + 1] = f2tf(v.y);
            As[arow + rr][acol + 2] = f2tf(v.z);
            As[arow + rr][acol + 3] = f2tf(v.w);
        }
        // W chunk 32x128
#pragma unroll
        for (int kk = wrow; kk < 32; kk += 8) {
            float4 w = *(const float4*)(W + (k0 + kk) * 128 + wcol);
            Ws[kk][wcol + 0] = f2tf(w.x);
            Ws[kk][wcol + 1] = f2tf(w.y);
            Ws[kk][wcol + 2] = f2tf(w.z);
            Ws[kk][wcol + 3] = f2tf(w.w);
        }
        __syncthreads();

#pragma unroll
        for (int ks = 0; ks < 4; ks++) {
            int kb = ks * 8;
            unsigned a[2][4];
#pragma unroll
            for (int mi = 0; mi < 2; mi++) {
                int rb = wm * 32 + mi * 16 + qr;
                a[mi][0] = As[rb][kb + qc];
                a[mi][1] = As[rb + 8][kb + qc];
                a[mi][2] = As[rb][kb + qc + 4];
                a[mi][3] = As[rb + 8][kb + qc + 4];
            }
#pragma unroll
            for (int ni = 0; ni < 8; ni++) {
                int n = wn * 64 + ni * 8 + qr;
                unsigned b0 = Ws[kb + qc][n];
                unsigned b1 = Ws[kb + qc + 4][n];
#pragma unroll
                for (int mi = 0; mi < 2; mi++) {
                    asm volatile(
                        "mma.sync.aligned.m16n8k8.row.col.f32.tf32.tf32.f32 "
                        "{%0,%1,%2,%3}, {%4,%5,%6,%7}, {%8,%9}, {%0,%1,%2,%3};\n"
                        : "+f"(acc[mi][ni][0]), "+f"(acc[mi][ni][1]),
                          "+f"(acc[mi][ni][2]), "+f"(acc[mi][ni][3])
                        : "r"(a[mi][0]), "r"(a[mi][1]), "r"(a[mi][2]), "r"(a[mi][3]),
                          "r"(b0), "r"(b1));
                }
            }
        }
        __syncthreads();
    }

    // epilogue
#pragma unroll
    for (int mi = 0; mi < 2; mi++) {
        int r0 = m0 + wm * 32 + mi * 16 + qr;
#pragma unroll
        for (int ni = 0; ni < 8; ni++) {
            int col = wn * 64 + ni * 8 + qc * 2;
            float bx = 0.f, by = 0.f;
            if (bvec) { bx = bvec[col]; by = bvec[col + 1]; }
            if (r0 < M) {
                float2 o; o.x = acc[mi][ni][0] + bx; o.y = acc[mi][ni][1] + by;
                *(float2*)(C + (long long)r0 * 128 + col) = o;
            }
            if (r0 + 8 < M) {
                float2 o; o.x = acc[mi][ni][2] + bx; o.y = acc[mi][ni][3] + by;
                *(float2*)(C + (long long)(r0 + 8) * 128 + col) = o;
            }
        }
    }
}

// ---------------- fused GATv2 edge pass + BN statistics + BN finalize ----------------
// one warp per destination node; lane l owns channels [4l, 4l+4); head = lane/8
#define GAT_STEP(ML)                                                        \
    {                                                                       \
        float px = (ML).x + xr4.x; px = px > 0.f ? px : px * SLOPE;         \
        float py = (ML).y + xr4.y; py = py > 0.f ? py : py * SLOPE;         \
        float pz = (ML).z + xr4.z; pz = pz > 0.f ? pz : pz * SLOPE;         \
        float pw = (ML).w + xr4.w; pw = pw > 0.f ? pw : pw * SLOPE;         \
        float part = px * a4.x + py * a4.y + pz * a4.z + pw * a4.w;         \
        part += __shfl_xor_sync(0xffffffffu, part, 1);                      \
        part += __shfl_xor_sync(0xffffffffu, part, 2);                      \
        part += __shfl_xor_sync(0xffffffffu, part, 4);                      \
        float mo = m;                                                       \
        m = fmaxf(m, part);                                                 \
        float cs = __expf(mo - m);                                          \
        float p  = __expf(part - m);                                        \
        s = s * cs + p;                                                     \
        acc.x = acc.x * cs + p * (ML).x;                                    \
        acc.y = acc.y * cs + p * (ML).y;                                    \
        acc.z = acc.z * cs + p * (ML).z;                                    \
        acc.w = acc.w * cs + p * (ML).w;                                    \
    }

__global__ void __launch_bounds__(512)
k_gat_bn(const float* __restrict__ xl, const float* __restrict__ xr,
         const float* __restrict__ xres, const float* __restrict__ att,
         const float* __restrict__ bias,
         const float* __restrict__ gamma, const float* __restrict__ beta,
         float* __restrict__ h, int N) {
    __shared__ float s_sum[128];
    __shared__ float s_sq[128];
    __shared__ int s_last;

    int tid = threadIdx.x;
    if (tid < 128) { s_sum[tid] = 0.f; s_sq[tid] = 0.f; }
    __syncthreads();

    int warp = (blockIdx.x * blockDim.x + tid) >> 5;
    int lane = tid & 31;

    if (warp < N) {
        int node = warp;
        float4 xr4 = *(const float4*)(xr + (long long)node * D + lane * 4);
        float4 a4  = *(const float4*)(att + lane * 4);

        int beg = g_rowptr[node];
        int end = g_rowptr[node + 1];

        float m = -3.0e38f, s = 0.f;
        float4 acc = make_float4(0.f, 0.f, 0.f, 0.f);

        int e = beg;
        for (; e + 4 <= end; e += 4) {
            int s0 = g_col[e];
            int s1 = g_col[e + 1];
            int s2 = g_col[e + 2];
            int s3 = g_col[e + 3];
            float4 ml0 = *(const float4*)(xl + (long long)s0 * D + lane * 4);
            float4 ml1 = *(const float4*)(xl + (long long)s1 * D + lane * 4);
            float4 ml2 = *(const float4*)(xl + (long long)s2 * D + lane * 4);
            float4 ml3 = *(const float4*)(xl + (long long)s3 * D + lane * 4);
            GAT_STEP(ml0);
            GAT_STEP(ml1);
            GAT_STEP(ml2);
            GAT_STEP(ml3);
        }
        for (; e < end; e++) {
            int s0 = g_col[e];
            float4 ml0 = *(const float4*)(xl + (long long)s0 * D + lane * 4);
            GAT_STEP(ml0);
        }

        float inv = 1.f / s;  // every node has a self loop => s > 0
        float4 b4 = *(const float4*)(bias + lane * 4);
        float4 r4 = *(const float4*)(xres + (long long)node * D + lane * 4);
        float4 o;
        o.x = acc.x * inv + b4.x + r4.x;
        o.y = acc.y * inv + b4.y + r4.y;
        o.z = acc.z * inv + b4.z + r4.z;
        o.w = acc.w * inv + b4.w + r4.w;
        *(float4*)(h + (long long)node * D + lane * 4) = o;

        // per-block BN partial sums (channels are lane-distinct => spread smem atomics)
        int c = lane * 4;
        atomicAdd(&s_sum[c + 0], o.x); atomicAdd(&s_sq[c + 0], o.x * o.x);
        atomicAdd(&s_sum[c + 1], o.y); atomicAdd(&s_sq[c + 1], o.y * o.y);
        atomicAdd(&s_sum[c + 2], o.z); atomicAdd(&s_sq[c + 2], o.z * o.z);
        atomicAdd(&s_sum[c + 3], o.w); atomicAdd(&s_sq[c + 3], o.w * o.w);
    }
    __syncthreads();

    if (tid < 128) {
        atomicAdd(&g_dsum[tid], (double)s_sum[tid]);
        atomicAdd(&g_dsq[tid],  (double)s_sq[tid]);
    }
    __threadfence();
    __syncthreads();
    if (tid == 0) {
        int t = atomicAdd(&g_ticket, 1);
        s_last = (t == (int)gridDim.x - 1) ? 1 : 0;
    }
    __syncthreads();

    if (s_last && tid < 128) {
        double mean = __ldcg(&g_dsum[tid]) / (double)N;
        double var  = __ldcg(&g_dsq[tid]) / (double)N - mean * mean;
        float inv = rsqrtf((float)var + BN_EPS);
        float sc = gamma[tid] * inv;
        g_scale[tid] = sc;
        g_shift[tid] = beta[tid] - (float)mean * sc;
    }
}

// ---------------- launch ----------------
extern "C" void kernel_launch(void* const* d_in, const int* in_sizes, int n_in,
                              void* d_out, int out_size) {
    const float* x     = (const float*)d_in[0];
    const void*  ei    = d_in[1];
    const float* Wl    = (const float*)d_in[2];
    const float* Wr    = (const float*)d_in[3];
    const float* att   = (const float*)d_in[4];
    const float* bias  = (const float*)d_in[5];
    const float* Wres  = (const float*)d_in[6];
    const float* gamma = (const float*)d_in[7];
    const float* beta  = (const float*)d_in[8];
    const float* Wout  = (const float*)d_in[9];
    const float* bout  = (const float*)d_in[10];
    int N = in_sizes[0] / D;
    int E = in_sizes[1] / 2;
    float* out = (float*)d_out;

    float *p_xl, *p_xr, *p_xres, *p_h;
    cudaGetSymbolAddress((void**)&p_xl, g_xl);
    cudaGetSymbolAddress((void**)&p_xr, g_xr);
    cudaGetSymbolAddress((void**)&p_xres, g_xres);
    cudaGetSymbolAddress((void**)&p_h, g_h);

    int Et = E + N;
    int nb = (N + 1023) / 1024;

    k_init<<<(N + 255) / 256, 256>>>((const unsigned int*)ei, N);
    k_count<<<(Et + 255) / 256, 256>>>(ei, E, N);
    k_scan1<<<nb, 1024>>>(N);
    k_scan3<<<nb, 1024>>>(N);
    k_scatter<<<(Et + 255) / 256, 256>>>(ei, E, N);

    int mtiles = (N + 127) / 128;
    dim3 g3(mtiles, 3);
    dim3 g1(mtiles, 1);
    int gatgrid = (N * 32 + 511) / 512;

    const float* xin = x;
    for (int l = 0; l < 3; l++) {
        int affine = (l > 0) ? 1 : 0;
        k_gemm3<<<g3, 256>>>(xin,
                             Wl + l * D * D, Wr + l * D * D, Wres + l * D * D,
                             p_xl, p_xr, p_xres, nullptr, N, affine);
        k_gat_bn<<<gatgrid, 512>>>(p_xl, p_xr, p_xres, att + l * D, bias + l * D,
                                   gamma + l * D, beta + l * D, p_h, N);
        xin = p_h;
    }
    k_gemm3<<<g1, 256>>>(p_h, Wout, Wout, Wout, out, out, out, bout, N, 1);
}

// round 5
// speedup vs baseline: 1.9682x; 1.0386x over previous
#include <cuda_runtime.h>
#include <math.h>

#define D 128
#define SLOPE 0.2f
#define BN_EPS 1e-5f
#define MAXN 50048
#define MAXET 901120

// ---------------- scratch (static device globals: allocation-free) ----------------
// g_deg / g_cursor are ZERO on entry to every call: zero at module load, and
// k_scan1 re-zeroes them immediately after consuming (self-restoring for graph replay).
__device__ __align__(16) float g_xl[MAXN * D];
__device__ __align__(16) float g_xr[MAXN * D];
__device__ __align__(16) float g_xres[MAXN * D];
__device__ __align__(16) float g_h[MAXN * D];
__device__ int g_deg[MAXN];
__device__ int g_cursor[MAXN];
__device__ int g_rowptr[MAXN + 1];
__device__ int g_col[MAXET];
__device__ int g_bsum[64];
__device__ double g_dsum[D];
__device__ double g_dsq[D];
__device__ __align__(16) float g_scale[D];
__device__ __align__(16) float g_shift[D];
__device__ int g_ticket;

// int64-vs-int32 probe: odd 32-bit words of the first 8 values all zero => int64.
// (int32 false positive needs 8 specific node ids == 0: prob ~(1/N)^8, negligible)
__device__ __forceinline__ int probe_is64(const unsigned int* __restrict__ p) {
    unsigned int o = 0;
#pragma unroll
    for (int j = 1; j < 16; j += 2) o |= p[j];
    return o == 0u;
}

// ---------------- CSR build ----------------
__global__ void k_count(const void* __restrict__ ei, int E, int N) {
    __shared__ int s64;
    if (threadIdx.x == 0) s64 = probe_is64((const unsigned int*)ei);
    __syncthreads();
    int is64 = s64;
    int t = blockIdx.x * blockDim.x + threadIdx.x;
    int Et = E + N;
    if (t >= Et) return;
    int d;
    if (t < E) {
        d = is64 ? (int)((const long long*)ei)[(long long)E + t]
                 : ((const int*)ei)[E + t];
    } else {
        d = t - E;  // self loop
    }
    atomicAdd(&g_deg[d], 1);
}

__global__ void k_scan1(int N) {
    __shared__ int s[1024];
    int tid = threadIdx.x;
    int i = blockIdx.x * 1024 + tid;
    int v = (i < N) ? g_deg[i] : 0;
    if (i < N) { g_deg[i] = 0; g_cursor[i] = 0; }  // restore zeros for this/next call
    s[tid] = v;
    __syncthreads();
    for (int off = 1; off < 1024; off <<= 1) {
        int t = 0;
        if (tid >= off) t = s[tid - off];
        __syncthreads();
        if (tid >= off) s[tid] += t;
        __syncthreads();
    }
    if (i < N) g_rowptr[i + 1] = s[tid];
    if (tid == 1023) g_bsum[blockIdx.x] = s[1023];
}

// scan of block totals done inline per block (<=49 iters), then add
__global__ void k_scan3(int N) {
    __shared__ int sbase;
    if (threadIdx.x == 0) {
        int acc = 0;
        for (int b = 0; b < blockIdx.x; b++) acc += g_bsum[b];
        sbase = acc;
    }
    __syncthreads();
    int i = blockIdx.x * 1024 + threadIdx.x;
    if (i < N) g_rowptr[i + 1] += sbase;
    if (i == 0) g_rowptr[0] = 0;
}

__global__ void k_scatter(const void* __restrict__ ei, int E, int N) {
    __shared__ int s64;
    if (threadIdx.x == 0) s64 = probe_is64((const unsigned int*)ei);
    __syncthreads();
    int is64 = s64;
    int t = blockIdx.x * blockDim.x + threadIdx.x;
    int Et = E + N;
    if (t >= Et) return;
    int s, d;
    if (t < E) {
        if (is64) {
            s = (int)((const long long*)ei)[t];
            d = (int)((const long long*)ei)[(long long)E + t];
        } else {
            s = ((const int*)ei)[t];
            d = ((const int*)ei)[E + t];
        }
    } else {
        s = d = t - E;
    }
    int pos = g_rowptr[d] + atomicAdd(&g_cursor[d], 1);
    g_col[pos] = s;
}

// ---------------- tf32 tensor-core GEMM ----------------
// C[M,128] = act(A)[M,128] @ W[128,128] (+bias)
// act = identity (affine==0) or per-column BN affine + leaky-relu (affine==1)
// Block: 256 threads (8 warps, 4x2), C tile 128x128, warp tile 32x64.
// Block (0,0) also zeroes the BN accumulators for the following k_gat_bn.
__device__ __forceinline__ unsigned f2tf(float x) {
    unsigned r;
    asm("cvt.rna.tf32.f32 %0, %1;" : "=r"(r) : "f"(x));
    return r;
}

__global__ void __launch_bounds__(256, 2)
k_gemm3(const float* __restrict__ A,
        const float* __restrict__ W0, const float* __restrict__ W1,
        const float* __restrict__ W2,
        float* __restrict__ C0, float* __restrict__ C1, float* __restrict__ C2,
        const float* __restrict__ bvec, int M, int affine) {
    const float* W = (blockIdx.y == 0) ? W0 : (blockIdx.y == 1 ? W1 : W2);
    float* C = (blockIdx.y == 0) ? C0 : (blockIdx.y == 1 ? C1 : C2);

    __shared__ unsigned As[128][36];   // padded: bank = 4r+c (conflict-free frags)
    __shared__ unsigned Ws[32][132];

    int tid = threadIdx.x;
    int warp = tid >> 5;
    int lane = tid & 31;

    // zero BN accumulators for the following fused GAT+BN kernel
    if (blockIdx.x == 0 && blockIdx.y == 0) {
        if (tid < 128) { g_dsum[tid] = 0.0; g_dsq[tid] = 0.0; }
        if (tid == 0) g_ticket = 0;
    }

    int wm = warp >> 1;           // 0..3  -> 32-row slab
    int wn = warp & 1;            // 0..1  -> 64-col slab
    int m0 = blockIdx.x * 128;

    int qr = lane >> 2;           // 0..7
    int qc = lane & 3;            // 0..3

    float acc[2][8][4];
#pragma unroll
    for (int i = 0; i < 2; i++)
#pragma unroll
        for (int j = 0; j < 8; j++)
#pragma unroll
            for (int k = 0; k < 4; k++) acc[i][j][k] = 0.f;

    int arow = tid >> 3;          // 0..31
    int acol = (tid & 7) * 4;     // 0..28
    int wrow = tid >> 5;          // 0..7
    int wcol = (tid & 31) * 4;    // 0..124

    for (int k0 = 0; k0 < 128; k0 += 32) {
        // A chunk 128x32
#pragma unroll
        for (int rr = 0; rr < 128; rr += 32) {
            int gm = m0 + arow + rr;
            float4 v = make_float4(0.f, 0.f, 0.f, 0.f);
            if (gm < M) v = *(const float4*)(A + (long long)gm * 128 + k0 + acol);
            if (affine) {
                float4 sc = *(const float4*)(g_scale + k0 + acol);
                float4 sh = *(const float4*)(g_shift + k0 + acol);
                v.x = fmaf(v.x, sc.x, sh.x); v.x = v.x > 0.f ? v.x : v.x * SLOPE;
                v.y = fmaf(v.y, sc.y, sh.y); v.y = v.y > 0.f ? v.y : v.y * SLOPE;
                v.z = fmaf(v.z, sc.z, sh.z); v.z = v.z > 0.f ? v.z : v.z * SLOPE;
                v.w = fmaf(v.w, sc.w, sh.w); v.w = v.w > 0.f ? v.w : v.w * SLOPE;
            }
            As[arow + rr][acol + 0] = f2tf(v.x);
            As[arow + rr][acol + 1] = f2tf(v.y);
            As[arow + rr][acol + 2] = f2tf(v.z);
            As[arow + rr][acol + 3] = f2tf(v.w);
        }
        // W chunk 32x128
#pragma unroll
        for (int kk = wrow; kk < 32; kk += 8) {
            float4 w = *(const float4*)(W + (k0 + kk) * 128 + wcol);
            Ws[kk][wcol + 0] = f2tf(w.x);
            Ws[kk][wcol + 1] = f2tf(w.y);
            Ws[kk][wcol + 2] = f2tf(w.z);
            Ws[kk][wcol + 3] = f2tf(w.w);
        }
        __syncthreads();

#pragma unroll
        for (int ks = 0; ks < 4; ks++) {
            int kb = ks * 8;
            unsigned a[2][4];
#pragma unroll
            for (int mi = 0; mi < 2; mi++) {
                int rb = wm * 32 + mi * 16 + qr;
                a[mi][0] = As[rb][kb + qc];
                a[mi][1] = As[rb + 8][kb + qc];
                a[mi][2] = As[rb][kb + qc + 4];
                a[mi][3] = As[rb + 8][kb + qc + 4];
            }
#pragma unroll
            for (int ni = 0; ni < 8; ni++) {
                int n = wn * 64 + ni * 8 + qr;
                unsigned b0 = Ws[kb + qc][n];
                unsigned b1 = Ws[kb + qc + 4][n];
#pragma unroll
                for (int mi = 0; mi < 2; mi++) {
                    asm volatile(
                        "mma.sync.aligned.m16n8k8.row.col.f32.tf32.tf32.f32 "
                        "{%0,%1,%2,%3}, {%4,%5,%6,%7}, {%8,%9}, {%0,%1,%2,%3};\n"
                        : "+f"(acc[mi][ni][0]), "+f"(acc[mi][ni][1]),
                          "+f"(acc[mi][ni][2]), "+f"(acc[mi][ni][3])
                        : "r"(a[mi][0]), "r"(a[mi][1]), "r"(a[mi][2]), "r"(a[mi][3]),
                          "r"(b0), "r"(b1));
                }
            }
        }
        __syncthreads();
    }

    // epilogue
#pragma unroll
    for (int mi = 0; mi < 2; mi++) {
        int r0 = m0 + wm * 32 + mi * 16 + qr;
#pragma unroll
        for (int ni = 0; ni < 8; ni++) {
            int col = wn * 64 + ni * 8 + qc * 2;
            float bx = 0.f, by = 0.f;
            if (bvec) { bx = bvec[col]; by = bvec[col + 1]; }
            if (r0 < M) {
                float2 o; o.x = acc[mi][ni][0] + bx; o.y = acc[mi][ni][1] + by;
                *(float2*)(C + (long long)r0 * 128 + col) = o;
            }
            if (r0 + 8 < M) {
                float2 o; o.x = acc[mi][ni][2] + bx; o.y = acc[mi][ni][3] + by;
                *(float2*)(C + (long long)(r0 + 8) * 128 + col) = o;
            }
        }
    }
}

// ---------------- fused GATv2 edge pass + BN statistics + BN finalize ----------------
// one warp per destination node; lane l owns channels [4l, 4l+4); head = lane/8
// Software-pipelined: per 4-edge batch, all scores + shfl reductions first
// (independent -> overlapped latencies), then the serial online-softmax updates.
__device__ __forceinline__ float gat_score(float4 ml, float4 xr4, float4 a4) {
    float px = ml.x + xr4.x; px = px > 0.f ? px : px * SLOPE;
    float py = ml.y + xr4.y; py = py > 0.f ? py : py * SLOPE;
    float pz = ml.z + xr4.z; pz = pz > 0.f ? pz : pz * SLOPE;
    float pw = ml.w + xr4.w; pw = pw > 0.f ? pw : pw * SLOPE;
    return px * a4.x + py * a4.y + pz * a4.z + pw * a4.w;
}

__global__ void __launch_bounds__(512)
k_gat_bn(const float* __restrict__ xl, const float* __restrict__ xr,
         const float* __restrict__ xres, const float* __restrict__ att,
         const float* __restrict__ bias,
         const float* __restrict__ gamma, const float* __restrict__ beta,
         float* __restrict__ h, int N) {
    __shared__ float s_sum[128];
    __shared__ float s_sq[128];
    __shared__ int s_last;

    int tid = threadIdx.x;
    if (tid < 128) { s_sum[tid] = 0.f; s_sq[tid] = 0.f; }
    __syncthreads();

    int warp = (blockIdx.x * blockDim.x + tid) >> 5;
    int lane = tid & 31;

    if (warp < N) {
        int node = warp;
        float4 xr4 = *(const float4*)(xr + (long long)node * D + lane * 4);
        float4 a4  = *(const float4*)(att + lane * 4);

        int beg = g_rowptr[node];
        int end = g_rowptr[node + 1];

        float m = -3.0e38f, s = 0.f;
        float4 acc = make_float4(0.f, 0.f, 0.f, 0.f);

        int e = beg;
        for (; e + 4 <= end; e += 4) {
            int si[4];
            si[0] = g_col[e];
            si[1] = g_col[e + 1];
            si[2] = g_col[e + 2];
            si[3] = g_col[e + 3];
            float4 ml[4];
#pragma unroll
            for (int j = 0; j < 4; j++)
                ml[j] = *(const float4*)(xl + (long long)si[j] * D + lane * 4);
            float pt[4];
#pragma unroll
            for (int j = 0; j < 4; j++) pt[j] = gat_score(ml[j], xr4, a4);
            // stage-interleaved shfl reductions (4 independent chains)
#pragma unroll
            for (int j = 0; j < 4; j++) pt[j] += __shfl_xor_sync(0xffffffffu, pt[j], 1);
#pragma unroll
            for (int j = 0; j < 4; j++) pt[j] += __shfl_xor_sync(0xffffffffu, pt[j], 2);
#pragma unroll
            for (int j = 0; j < 4; j++) pt[j] += __shfl_xor_sync(0xffffffffu, pt[j], 4);
            // online softmax updates (short fmax/acc chains only)
#pragma unroll
            for (int j = 0; j < 4; j++) {
                float mo = m;
                m = fmaxf(m, pt[j]);
                float cs = __expf(mo - m);
                float p  = __expf(pt[j] - m);
                s = s * cs + p;
                acc.x = acc.x * cs + p * ml[j].x;
                acc.y = acc.y * cs + p * ml[j].y;
                acc.z = acc.z * cs + p * ml[j].z;
                acc.w = acc.w * cs + p * ml[j].w;
            }
        }
        for (; e < end; e++) {
            int s0 = g_col[e];
            float4 ml0 = *(const float4*)(xl + (long long)s0 * D + lane * 4);
            float pt = gat_score(ml0, xr4, a4);
            pt += __shfl_xor_sync(0xffffffffu, pt, 1);
            pt += __shfl_xor_sync(0xffffffffu, pt, 2);
            pt += __shfl_xor_sync(0xffffffffu, pt, 4);
            float mo = m;
            m = fmaxf(m, pt);
            float cs = __expf(mo - m);
            float p  = __expf(pt - m);
            s = s * cs + p;
            acc.x = acc.x * cs + p * ml0.x;
            acc.y = acc.y * cs + p * ml0.y;
            acc.z = acc.z * cs + p * ml0.z;
            acc.w = acc.w * cs + p * ml0.w;
        }

        float inv = 1.f / s;  // every node has a self loop => s > 0
        float4 b4 = *(const float4*)(bias + lane * 4);
        float4 r4 = *(const float4*)(xres + (long long)node * D + lane * 4);
        float4 o;
        o.x = acc.x * inv + b4.x + r4.x;
        o.y = acc.y * inv + b4.y + r4.y;
        o.z = acc.z * inv + b4.z + r4.z;
        o.w = acc.w * inv + b4.w + r4.w;
        *(float4*)(h + (long long)node * D + lane * 4) = o;

        // per-block BN partial sums (channels are lane-distinct => spread smem atomics)
        int c = lane * 4;
        atomicAdd(&s_sum[c + 0], o.x); atomicAdd(&s_sq[c + 0], o.x * o.x);
        atomicAdd(&s_sum[c + 1], o.y); atomicAdd(&s_sq[c + 1], o.y * o.y);
        atomicAdd(&s_sum[c + 2], o.z); atomicAdd(&s_sq[c + 2], o.z * o.z);
        atomicAdd(&s_sum[c + 3], o.w); atomicAdd(&s_sq[c + 3], o.w * o.w);
    }
    __syncthreads();

    if (tid < 128) {
        atomicAdd(&g_dsum[tid], (double)s_sum[tid]);
        atomicAdd(&g_dsq[tid],  (double)s_sq[tid]);
    }
    __threadfence();
    __syncthreads();
    if (tid == 0) {
        int t = atomicAdd(&g_ticket, 1);
        s_last = (t == (int)gridDim.x - 1) ? 1 : 0;
    }
    __syncthreads();

    if (s_last && tid < 128) {
        double mean = __ldcg(&g_dsum[tid]) / (double)N;
        double var  = __ldcg(&g_dsq[tid]) / (double)N - mean * mean;
        float inv = rsqrtf((float)var + BN_EPS);
        float sc = gamma[tid] * inv;
        g_scale[tid] = sc;
        g_shift[tid] = beta[tid] - (float)mean * sc;
    }
}

// ---------------- launch ----------------
extern "C" void kernel_launch(void* const* d_in, const int* in_sizes, int n_in,
                              void* d_out, int out_size) {
    const float* x     = (const float*)d_in[0];
    const void*  ei    = d_in[1];
    const float* Wl    = (const float*)d_in[2];
    const float* Wr    = (const float*)d_in[3];
    const float* att   = (const float*)d_in[4];
    const float* bias  = (const float*)d_in[5];
    const float* Wres  = (const float*)d_in[6];
    const float* gamma = (const float*)d_in[7];
    const float* beta  = (const float*)d_in[8];
    const float* Wout  = (const float*)d_in[9];
    const float* bout  = (const float*)d_in[10];
    int N = in_sizes[0] / D;
    int E = in_sizes[1] / 2;
    float* out = (float*)d_out;

    float *p_xl, *p_xr, *p_xres, *p_h;
    cudaGetSymbolAddress((void**)&p_xl, g_xl);
    cudaGetSymbolAddress((void**)&p_xr, g_xr);
    cudaGetSymbolAddress((void**)&p_xres, g_xres);
    cudaGetSymbolAddress((void**)&p_h, g_h);

    // side stream + events, created once (host objects only — no device memory)
    static cudaStream_t s2 = []() {
        cudaStream_t s; cudaStreamCreateWithFlags(&s, cudaStreamNonBlocking); return s;
    }();
    static cudaEvent_t ev_fork = []() {
        cudaEvent_t e; cudaEventCreateWithFlags(&e, cudaEventDisableTiming); return e;
    }();
    static cudaEvent_t ev_csr = []() {
        cudaEvent_t e; cudaEventCreateWithFlags(&e, cudaEventDisableTiming); return e;
    }();

    int Et = E + N;
    int nb = (N + 1023) / 1024;

    // fork: CSR build on s2, overlapped with layer-0 GEMM on the main stream
    cudaEventRecord(ev_fork, 0);
    cudaStreamWaitEvent(s2, ev_fork, 0);
    k_count<<<(Et + 255) / 256, 256, 0, s2>>>(ei, E, N);
    k_scan1<<<nb, 1024, 0, s2>>>(N);
    k_scan3<<<nb, 1024, 0, s2>>>(N);
    k_scatter<<<(Et + 255) / 256, 256, 0, s2>>>(ei, E, N);
    cudaEventRecord(ev_csr, s2);

    int mtiles = (N + 127) / 128;
    dim3 g3(mtiles, 3);
    dim3 g1(mtiles, 1);
    int gatgrid = (N * 32 + 511) / 512;

    const float* xin = x;
    for (int l = 0; l < 3; l++) {
        int affine = (l > 0) ? 1 : 0;
        k_gemm3<<<g3, 256>>>(xin,
                             Wl + l * D * D, Wr + l * D * D, Wres + l * D * D,
                             p_xl, p_xr, p_xres, nullptr, N, affine);
        if (l == 0) cudaStreamWaitEvent(0, ev_csr, 0);  // join CSR before first edge pass
        k_gat_bn<<<gatgrid, 512>>>(p_xl, p_xr, p_xres, att + l * D, bias + l * D,
                                   gamma + l * D, beta + l * D, p_h, N);
        xin = p_h;
    }
    k_gemm3<<<g1, 256>>>(p_h, Wout, Wout, Wout, out, out, out, bout, N, 1);
}

// round 6
// speedup vs baseline: 1.9912x; 1.0117x over previous
#include <cuda_runtime.h>
#include <math.h>

#define D 128
#define SLOPE 0.2f
#define BN_EPS 1e-5f
#define MAXN 50048
#define MAXET 901120

// GEMM tile config: 256-row M tile, full K=128 resident in smem
#define GM_MT 256
#define GM_AS_STRIDE 132
#define GM_SMEM_BYTES ((GM_MT * GM_AS_STRIDE + 128 * GM_AS_STRIDE) * 4)

// ---------------- scratch (static device globals: allocation-free) ----------------
// g_deg / g_cursor are ZERO on entry to every call: zero at module load, and
// k_scan1 re-zeroes them immediately after consuming (self-restoring for graph replay).
__device__ __align__(16) float g_xl[MAXN * D];
__device__ __align__(16) float g_xr[MAXN * D];
__device__ __align__(16) float g_xres[MAXN * D];
__device__ __align__(16) float g_h[MAXN * D];
__device__ int g_deg[MAXN];
__device__ int g_cursor[MAXN];
__device__ int g_rowptr[MAXN + 1];
__device__ int g_col[MAXET];
__device__ int g_bsum[64];
__device__ double g_dsum[D];
__device__ double g_dsq[D];
__device__ __align__(16) float g_scale[D];
__device__ __align__(16) float g_shift[D];
__device__ int g_ticket;

// int64-vs-int32 probe: odd 32-bit words of the first 8 values all zero => int64.
__device__ __forceinline__ int probe_is64(const unsigned int* __restrict__ p) {
    unsigned int o = 0;
#pragma unroll
    for (int j = 1; j < 16; j += 2) o |= p[j];
    return o == 0u;
}

// ---------------- CSR build ----------------
__global__ void k_count(const void* __restrict__ ei, int E, int N) {
    __shared__ int s64;
    if (threadIdx.x == 0) s64 = probe_is64((const unsigned int*)ei);
    __syncthreads();
    int is64 = s64;
    int t = blockIdx.x * blockDim.x + threadIdx.x;
    int Et = E + N;
    if (t >= Et) return;
    int d;
    if (t < E) {
        d = is64 ? (int)((const long long*)ei)[(long long)E + t]
                 : ((const int*)ei)[E + t];
    } else {
        d = t - E;  // self loop
    }
    atomicAdd(&g_deg[d], 1);
}

__global__ void k_scan1(int N) {
    __shared__ int s[1024];
    int tid = threadIdx.x;
    int i = blockIdx.x * 1024 + tid;
    int v = (i < N) ? g_deg[i] : 0;
    if (i < N) { g_deg[i] = 0; g_cursor[i] = 0; }  // restore zeros for next call
    s[tid] = v;
    __syncthreads();
    for (int off = 1; off < 1024; off <<= 1) {
        int t = 0;
        if (tid >= off) t = s[tid - off];
        __syncthreads();
        if (tid >= off) s[tid] += t;
        __syncthreads();
    }
    if (i < N) g_rowptr[i + 1] = s[tid];
    if (tid == 1023) g_bsum[blockIdx.x] = s[1023];
}

__global__ void k_scan3(int N) {
    __shared__ int sbase;
    if (threadIdx.x == 0) {
        int acc = 0;
        for (int b = 0; b < blockIdx.x; b++) acc += g_bsum[b];
        sbase = acc;
    }
    __syncthreads();
    int i = blockIdx.x * 1024 + threadIdx.x;
    if (i < N) g_rowptr[i + 1] += sbase;
    if (i == 0) g_rowptr[0] = 0;
}

__global__ void k_scatter(const void* __restrict__ ei, int E, int N) {
    __shared__ int s64;
    if (threadIdx.x == 0) s64 = probe_is64((const unsigned int*)ei);
    __syncthreads();
    int is64 = s64;
    int t = blockIdx.x * blockDim.x + threadIdx.x;
    int Et = E + N;
    if (t >= Et) return;
    int s, d;
    if (t < E) {
        if (is64) {
            s = (int)((const long long*)ei)[t];
            d = (int)((const long long*)ei)[(long long)E + t];
        } else {
            s = ((const int*)ei)[t];
            d = ((const int*)ei)[E + t];
        }
    } else {
        s = d = t - E;
    }
    int pos = g_rowptr[d] + atomicAdd(&g_cursor[d], 1);
    g_col[pos] = s;
}

// ---------------- tf32 tensor-core GEMM (whole-K, single sync) ----------------
// C[M,128] = act(A)[M,128] @ W[128,128] (+bias)
// Block: 512 threads (16 warps, 8x2), C tile 256x128, warp tile 32x64.
// Full A tile (256x128) + full W (128x128) in dynamic smem; ONE barrier.
__device__ __forceinline__ unsigned f2tf(float x) {
    unsigned r;
    asm("cvt.rna.tf32.f32 %0, %1;" : "=r"(r) : "f"(x));
    return r;
}

__global__ void __launch_bounds__(512, 1)
k_gemm3(const float* __restrict__ A,
        const float* __restrict__ W0, const float* __restrict__ W1,
        const float* __restrict__ W2,
        float* __restrict__ C0, float* __restrict__ C1, float* __restrict__ C2,
        const float* __restrict__ bvec, int M, int affine) {
    const float* W = (blockIdx.y == 0) ? W0 : (blockIdx.y == 1 ? W1 : W2);
    float* C = (blockIdx.y == 0) ? C0 : (blockIdx.y == 1 ? C1 : C2);

    extern __shared__ unsigned smem_u[];
    unsigned* As = smem_u;                            // [256][132]
    unsigned* Ws = smem_u + GM_MT * GM_AS_STRIDE;     // [128][132]

    int tid = threadIdx.x;
    int warp = tid >> 5;
    int lane = tid & 31;

    // zero BN accumulators for the following fused GAT+BN kernel
    if (blockIdx.x == 0 && blockIdx.y == 0) {
        if (tid < 128) { g_dsum[tid] = 0.0; g_dsq[tid] = 0.0; }
        if (tid == 0) g_ticket = 0;
    }

    int wm = warp >> 1;           // 0..7  -> 32-row slab
    int wn = warp & 1;            // 0..1  -> 64-col slab
    int m0 = blockIdx.x * GM_MT;

    int qr = lane >> 2;           // 0..7
    int qc = lane & 3;            // 0..3

    // ---- load full A tile (256 x 128) ----
#pragma unroll
    for (int it = 0; it < 16; it++) {
        int i = it * 512 + tid;           // 0..8191
        int row = i >> 5;                 // 0..255
        int col = (i & 31) * 4;           // 0..124
        int gm = m0 + row;
        float4 v = make_float4(0.f, 0.f, 0.f, 0.f);
        if (gm < M) v = *(const float4*)(A + (long long)gm * 128 + col);
        if (affine) {
            float4 sc = *(const float4*)(g_scale + col);
            float4 sh = *(const float4*)(g_shift + col);
            v.x = fmaf(v.x, sc.x, sh.x); v.x = v.x > 0.f ? v.x : v.x * SLOPE;
            v.y = fmaf(v.y, sc.y, sh.y); v.y = v.y > 0.f ? v.y : v.y * SLOPE;
            v.z = fmaf(v.z, sc.z, sh.z); v.z = v.z > 0.f ? v.z : v.z * SLOPE;
            v.w = fmaf(v.w, sc.w, sh.w); v.w = v.w > 0.f ? v.w : v.w * SLOPE;
        }
        unsigned* dst = As + row * GM_AS_STRIDE + col;
        dst[0] = f2tf(v.x); dst[1] = f2tf(v.y); dst[2] = f2tf(v.z); dst[3] = f2tf(v.w);
    }
    // ---- load full W (128 x 128) ----
#pragma unroll
    for (int it = 0; it < 8; it++) {
        int i = it * 512 + tid;           // 0..4095
        int row = i >> 5;                 // 0..127
        int col = (i & 31) * 4;
        float4 w = *(const float4*)(W + row * 128 + col);
        unsigned* dst = Ws + row * GM_AS_STRIDE + col;
        dst[0] = f2tf(w.x); dst[1] = f2tf(w.y); dst[2] = f2tf(w.z); dst[3] = f2tf(w.w);
    }
    __syncthreads();

    float acc[2][8][4];
#pragma unroll
    for (int i = 0; i < 2; i++)
#pragma unroll
        for (int j = 0; j < 8; j++)
#pragma unroll
            for (int k = 0; k < 4; k++) acc[i][j][k] = 0.f;

#pragma unroll
    for (int ks = 0; ks < 16; ks++) {
        int kb = ks * 8;
        unsigned a[2][4];
#pragma unroll
        for (int mi = 0; mi < 2; mi++) {
            int rb = wm * 32 + mi * 16 + qr;
            const unsigned* ap = As + rb * GM_AS_STRIDE + kb + qc;
            a[mi][0] = ap[0];
            a[mi][1] = ap[8 * GM_AS_STRIDE];
            a[mi][2] = ap[4];
            a[mi][3] = ap[8 * GM_AS_STRIDE + 4];
        }
#pragma unroll
        for (int ni = 0; ni < 8; ni++) {
            int n = wn * 64 + ni * 8 + qr;
            unsigned b0 = Ws[(kb + qc) * GM_AS_STRIDE + n];
            unsigned b1 = Ws[(kb + qc + 4) * GM_AS_STRIDE + n];
#pragma unroll
            for (int mi = 0; mi < 2; mi++) {
                asm volatile(
                    "mma.sync.aligned.m16n8k8.row.col.f32.tf32.tf32.f32 "
                    "{%0,%1,%2,%3}, {%4,%5,%6,%7}, {%8,%9}, {%0,%1,%2,%3};\n"
                    : "+f"(acc[mi][ni][0]), "+f"(acc[mi][ni][1]),
                      "+f"(acc[mi][ni][2]), "+f"(acc[mi][ni][3])
                    : "r"(a[mi][0]), "r"(a[mi][1]), "r"(a[mi][2]), "r"(a[mi][3]),
                      "r"(b0), "r"(b1));
            }
        }
    }

    // epilogue
#pragma unroll
    for (int mi = 0; mi < 2; mi++) {
        int r0 = m0 + wm * 32 + mi * 16 + qr;
#pragma unroll
        for (int ni = 0; ni < 8; ni++) {
            int col = wn * 64 + ni * 8 + qc * 2;
            float bx = 0.f, by = 0.f;
            if (bvec) { bx = bvec[col]; by = bvec[col + 1]; }
            if (r0 < M) {
                float2 o; o.x = acc[mi][ni][0] + bx; o.y = acc[mi][ni][1] + by;
                *(float2*)(C + (long long)r0 * 128 + col) = o;
            }
            if (r0 + 8 < M) {
                float2 o; o.x = acc[mi][ni][2] + bx; o.y = acc[mi][ni][3] + by;
                *(float2*)(C + (long long)(r0 + 8) * 128 + col) = o;
            }
        }
    }
}

// ---------------- fused GATv2 edge pass + BN statistics + BN finalize ----------------
// one warp per destination node; lane l owns channels [4l, 4l+4); head = lane/8
// Cross-batch software pipeline: prefetch batch i+1's gathered rows while
// executing batch i's score/softmax math.
__device__ __forceinline__ float gat_score(float4 ml, float4 xr4, float4 a4) {
    float px = ml.x + xr4.x; px = px > 0.f ? px : px * SLOPE;
    float py = ml.y + xr4.y; py = py > 0.f ? py : py * SLOPE;
    float pz = ml.z + xr4.z; pz = pz > 0.f ? pz : pz * SLOPE;
    float pw = ml.w + xr4.w; pw = pw > 0.f ? pw : pw * SLOPE;
    return px * a4.x + py * a4.y + pz * a4.z + pw * a4.w;
}

__global__ void __launch_bounds__(512)
k_gat_bn(const float* __restrict__ xl, const float* __restrict__ xr,
         const float* __restrict__ xres, const float* __restrict__ att,
         const float* __restrict__ bias,
         const float* __restrict__ gamma, const float* __restrict__ beta,
         float* __restrict__ h, int N) {
    __shared__ float s_sum[128];
    __shared__ float s_sq[128];
    __shared__ int s_last;

    int tid = threadIdx.x;
    if (tid < 128) { s_sum[tid] = 0.f; s_sq[tid] = 0.f; }
    __syncthreads();

    int warp = (blockIdx.x * blockDim.x + tid) >> 5;
    int lane = tid & 31;

    if (warp < N) {
        int node = warp;
        float4 xr4 = *(const float4*)(xr + (long long)node * D + lane * 4);
        float4 a4  = *(const float4*)(att + lane * 4);

        int beg = g_rowptr[node];
        int end = g_rowptr[node + 1];

        float m = -3.0e38f, s = 0.f;
        float4 acc = make_float4(0.f, 0.f, 0.f, 0.f);

        int nfull = (end - beg) & ~3;
        int efin = beg + nfull;

        float4 cur[4];
        if (nfull) {
            // prologue: gather first batch
#pragma unroll
            for (int j = 0; j < 4; j++) {
                int si = g_col[beg + j];
                cur[j] = *(const float4*)(xl + (long long)si * D + lane * 4);
            }
            for (int e = beg + 4; e <= efin; e += 4) {
                float4 nxt[4];
                bool more = (e < efin);
                if (more) {
                    // prefetch next batch (independent of current math)
#pragma unroll
                    for (int j = 0; j < 4; j++) {
                        int si = g_col[e + j];
                        nxt[j] = *(const float4*)(xl + (long long)si * D + lane * 4);
                    }
                }
                // process current batch
                float pt[4];
#pragma unroll
                for (int j = 0; j < 4; j++) pt[j] = gat_score(cur[j], xr4, a4);
#pragma unroll
                for (int j = 0; j < 4; j++) pt[j] += __shfl_xor_sync(0xffffffffu, pt[j], 1);
#pragma unroll
                for (int j = 0; j < 4; j++) pt[j] += __shfl_xor_sync(0xffffffffu, pt[j], 2);
#pragma unroll
                for (int j = 0; j < 4; j++) pt[j] += __shfl_xor_sync(0xffffffffu, pt[j], 4);
#pragma unroll
                for (int j = 0; j < 4; j++) {
                    float mo = m;
                    m = fmaxf(m, pt[j]);
                    float cs = __expf(mo - m);
                    float p  = __expf(pt[j] - m);
                    s = s * cs + p;
                    acc.x = acc.x * cs + p * cur[j].x;
                    acc.y = acc.y * cs + p * cur[j].y;
                    acc.z = acc.z * cs + p * cur[j].z;
                    acc.w = acc.w * cs + p * cur[j].w;
                }
                if (more) {
#pragma unroll
                    for (int j = 0; j < 4; j++) cur[j] = nxt[j];
                }
            }
        }
        // remainder (0..3 edges)
        for (int e = efin; e < end; e++) {
            int s0 = g_col[e];
            float4 ml0 = *(const float4*)(xl + (long long)s0 * D + lane * 4);
            float pt = gat_score(ml0, xr4, a4);
            pt += __shfl_xor_sync(0xffffffffu, pt, 1);
            pt += __shfl_xor_sync(0xffffffffu, pt, 2);
            pt += __shfl_xor_sync(0xffffffffu, pt, 4);
            float mo = m;
            m = fmaxf(m, pt);
            float cs = __expf(mo - m);
            float p  = __expf(pt - m);
            s = s * cs + p;
            acc.x = acc.x * cs + p * ml0.x;
            acc.y = acc.y * cs + p * ml0.y;
            acc.z = acc.z * cs + p * ml0.z;
            acc.w = acc.w * cs + p * ml0.w;
        }

        float inv = 1.f / s;  // every node has a self loop => s > 0
        float4 b4 = *(const float4*)(bias + lane * 4);
        float4 r4 = *(const float4*)(xres + (long long)node * D + lane * 4);
        float4 o;
        o.x = acc.x * inv + b4.x + r4.x;
        o.y = acc.y * inv + b4.y + r4.y;
        o.z = acc.z * inv + b4.z + r4.z;
        o.w = acc.w * inv + b4.w + r4.w;
        *(float4*)(h + (long long)node * D + lane * 4) = o;

        int c = lane * 4;
        atomicAdd(&s_sum[c + 0], o.x); atomicAdd(&s_sq[c + 0], o.x * o.x);
        atomicAdd(&s_sum[c + 1], o.y); atomicAdd(&s_sq[c + 1], o.y * o.y);
        atomicAdd(&s_sum[c + 2], o.z); atomicAdd(&s_sq[c + 2], o.z * o.z);
        atomicAdd(&s_sum[c + 3], o.w); atomicAdd(&s_sq[c + 3], o.w * o.w);
    }
    __syncthreads();

    if (tid < 128) {
        atomicAdd(&g_dsum[tid], (double)s_sum[tid]);
        atomicAdd(&g_dsq[tid],  (double)s_sq[tid]);
    }
    __threadfence();
    __syncthreads();
    if (tid == 0) {
        int t = atomicAdd(&g_ticket, 1);
        s_last = (t == (int)gridDim.x - 1) ? 1 : 0;
    }
    __syncthreads();

    if (s_last && tid < 128) {
        double mean = __ldcg(&g_dsum[tid]) / (double)N;
        double var  = __ldcg(&g_dsq[tid]) / (double)N - mean * mean;
        float inv = rsqrtf((float)var + BN_EPS);
        float sc = gamma[tid] * inv;
        g_scale[tid] = sc;
        g_shift[tid] = beta[tid] - (float)mean * sc;
    }
}

// ---------------- launch ----------------
extern "C" void kernel_launch(void* const* d_in, const int* in_sizes, int n_in,
                              void* d_out, int out_size) {
    const float* x     = (const float*)d_in[0];
    const void*  ei    = d_in[1];
    const float* Wl    = (const float*)d_in[2];
    const float* Wr    = (const float*)d_in[3];
    const float* att   = (const float*)d_in[4];
    const float* bias  = (const float*)d_in[5];
    const float* Wres  = (const float*)d_in[6];
    const float* gamma = (const float*)d_in[7];
    const float* beta  = (const float*)d_in[8];
    const float* Wout  = (const float*)d_in[9];
    const float* bout  = (const float*)d_in[10];
    int N = in_sizes[0] / D;
    int E = in_sizes[1] / 2;
    float* out = (float*)d_out;

    float *p_xl, *p_xr, *p_xres, *p_h;
    cudaGetSymbolAddress((void**)&p_xl, g_xl);
    cudaGetSymbolAddress((void**)&p_xr, g_xr);
    cudaGetSymbolAddress((void**)&p_xres, g_xres);
    cudaGetSymbolAddress((void**)&p_h, g_h);

    static cudaStream_t s2 = []() {
        cudaStream_t s; cudaStreamCreateWithFlags(&s, cudaStreamNonBlocking); return s;
    }();
    static cudaEvent_t ev_fork = []() {
        cudaEvent_t e; cudaEventCreateWithFlags(&e, cudaEventDisableTiming); return e;
    }();
    static cudaEvent_t ev_csr = []() {
        cudaEvent_t e; cudaEventCreateWithFlags(&e, cudaEventDisableTiming); return e;
    }();
    static bool attr_ok = []() {
        cudaFuncSetAttribute(k_gemm3, cudaFuncAttributeMaxDynamicSharedMemorySize,
                             GM_SMEM_BYTES);
        return true;
    }();
    (void)attr_ok;

    int Et = E + N;
    int nb = (N + 1023) / 1024;

    int mtiles = (N + GM_MT - 1) / GM_MT;
    dim3 g3(mtiles, 3);
    dim3 g1(mtiles, 1);
    int gatgrid = (N * 32 + 511) / 512;

    // enqueue order: gemm3 L0 first (=> ncu -s 5 lands on k_gat_bn L0),
    // CSR chain forked onto s2 runs concurrently with it.
    cudaEventRecord(ev_fork, 0);
    k_gemm3<<<g3, 512, GM_SMEM_BYTES>>>(x,
                                        Wl, Wr, Wres,
                                        p_xl, p_xr, p_xres, nullptr, N, 0);
    cudaStreamWaitEvent(s2, ev_fork, 0);
    k_count<<<(Et + 255) / 256, 256, 0, s2>>>(ei, E, N);
    k_scan1<<<nb, 1024, 0, s2>>>(N);
    k_scan3<<<nb, 1024, 0, s2>>>(N);
    k_scatter<<<(Et + 255) / 256, 256, 0, s2>>>(ei, E, N);
    cudaEventRecord(ev_csr, s2);
    cudaStreamWaitEvent(0, ev_csr, 0);  // join CSR before first edge pass

    const float* xin = x;
    for (int l = 0; l < 3; l++) {
        if (l > 0) {
            k_gemm3<<<g3, 512, GM_SMEM_BYTES>>>(xin,
                                                Wl + l * D * D, Wr + l * D * D,
                                                Wres + l * D * D,
                                                p_xl, p_xr, p_xres, nullptr, N, 1);
        }
        k_gat_bn<<<gatgrid, 512>>>(p_xl, p_xr, p_xres, att + l * D, bias + l * D,
                                   gamma + l * D, beta + l * D, p_h, N);
        xin = p_h;
    }
    k_gemm3<<<g1, 512, GM_SMEM_BYTES>>>(p_h, Wout, Wout, Wout, out, out, out, bout, N, 1);
}

// round 7
// speedup vs baseline: 2.4643x; 1.2376x over previous
#include <cuda_runtime.h>
#include <math.h>

#define D 128
#define SLOPE 0.2f
#define BN_EPS 1e-5f
#define MAXN 50048
#define MAXET 901120

// GEMM tile config: 256-row M tile, full K=128 resident in smem
#define GM_MT 256
#define GM_AS_STRIDE 132
#define GM_SMEM_BYTES ((GM_MT * GM_AS_STRIDE + 128 * GM_AS_STRIDE) * 4)

// GAT kernel launch shape: pooled strided warp scheduling
#define GAT_BLOCKS 592
#define GAT_THREADS 256
#define GAT_WARPS (GAT_BLOCKS * (GAT_THREADS / 32))

// ---------------- scratch (static device globals: allocation-free) ----------------
// g_deg / g_cursor are ZERO on entry to every call: zero at module load, and
// k_scan1 re-zeroes them immediately after consuming (self-restoring for graph replay).
__device__ __align__(16) float g_xl[MAXN * D];
__device__ __align__(16) float g_xr[MAXN * D];
__device__ __align__(16) float g_xres[MAXN * D];
__device__ __align__(16) float g_h[MAXN * D];
__device__ int g_deg[MAXN];
__device__ int g_cursor[MAXN];
__device__ int g_rowptr[MAXN + 1];
__device__ int g_col[MAXET];
__device__ int g_bsum[64];
__device__ double g_dsum[D];
__device__ double g_dsq[D];
__device__ __align__(16) float g_scale[D];
__device__ __align__(16) float g_shift[D];
__device__ int g_ticket;

// int64-vs-int32 probe: odd 32-bit words of the first 8 values all zero => int64.
__device__ __forceinline__ int probe_is64(const unsigned int* __restrict__ p) {
    unsigned int o = 0;
#pragma unroll
    for (int j = 1; j < 16; j += 2) o |= p[j];
    return o == 0u;
}

// ---------------- CSR build ----------------
__global__ void k_count(const void* __restrict__ ei, int E, int N) {
    __shared__ int s64;
    if (threadIdx.x == 0) s64 = probe_is64((const unsigned int*)ei);
    __syncthreads();
    int is64 = s64;
    int t = blockIdx.x * blockDim.x + threadIdx.x;
    int Et = E + N;
    if (t >= Et) return;
    int d;
    if (t < E) {
        d = is64 ? (int)((const long long*)ei)[(long long)E + t]
                 : ((const int*)ei)[E + t];
    } else {
        d = t - E;  // self loop
    }
    atomicAdd(&g_deg[d], 1);
}

__global__ void k_scan1(int N) {
    __shared__ int s[1024];
    int tid = threadIdx.x;
    int i = blockIdx.x * 1024 + tid;
    int v = (i < N) ? g_deg[i] : 0;
    if (i < N) { g_deg[i] = 0; g_cursor[i] = 0; }  // restore zeros for next call
    s[tid] = v;
    __syncthreads();
    for (int off = 1; off < 1024; off <<= 1) {
        int t = 0;
        if (tid >= off) t = s[tid - off];
        __syncthreads();
        if (tid >= off) s[tid] += t;
        __syncthreads();
    }
    if (i < N) g_rowptr[i + 1] = s[tid];
    if (tid == 1023) g_bsum[blockIdx.x] = s[1023];
}

__global__ void k_scan3(int N) {
    __shared__ int sbase;
    if (threadIdx.x == 0) {
        int acc = 0;
        for (int b = 0; b < blockIdx.x; b++) acc += g_bsum[b];
        sbase = acc;
    }
    __syncthreads();
    int i = blockIdx.x * 1024 + threadIdx.x;
    if (i < N) g_rowptr[i + 1] += sbase;
    if (i == 0) g_rowptr[0] = 0;
}

__global__ void k_scatter(const void* __restrict__ ei, int E, int N) {
    __shared__ int s64;
    if (threadIdx.x == 0) s64 = probe_is64((const unsigned int*)ei);
    __syncthreads();
    int is64 = s64;
    int t = blockIdx.x * blockDim.x + threadIdx.x;
    int Et = E + N;
    if (t >= Et) return;
    int s, d;
    if (t < E) {
        if (is64) {
            s = (int)((const long long*)ei)[t];
            d = (int)((const long long*)ei)[(long long)E + t];
        } else {
            s = ((const int*)ei)[t];
            d = ((const int*)ei)[E + t];
        }
    } else {
        s = d = t - E;
    }
    int pos = g_rowptr[d] + atomicAdd(&g_cursor[d], 1);
    g_col[pos] = s;
}

// ---------------- tf32 tensor-core GEMM (whole-K, single sync) ----------------
// C[M,128] = act(A)[M,128] @ W[128,128] (+bias)
// Block: 512 threads (16 warps, 8x2), C tile 256x128, warp tile 32x64.
__device__ __forceinline__ unsigned f2tf(float x) {
    unsigned r;
    asm("cvt.rna.tf32.f32 %0, %1;" : "=r"(r) : "f"(x));
    return r;
}

__global__ void __launch_bounds__(512, 1)
k_gemm3(const float* __restrict__ A,
        const float* __restrict__ W0, const float* __restrict__ W1,
        const float* __restrict__ W2,
        float* __restrict__ C0, float* __restrict__ C1, float* __restrict__ C2,
        const float* __restrict__ bvec, int M, int affine) {
    const float* W = (blockIdx.y == 0) ? W0 : (blockIdx.y == 1 ? W1 : W2);
    float* C = (blockIdx.y == 0) ? C0 : (blockIdx.y == 1 ? C1 : C2);

    extern __shared__ unsigned smem_u[];
    unsigned* As = smem_u;                            // [256][132]
    unsigned* Ws = smem_u + GM_MT * GM_AS_STRIDE;     // [128][132]

    int tid = threadIdx.x;
    int warp = tid >> 5;
    int lane = tid & 31;

    // zero BN accumulators for the following fused GAT+BN kernel
    if (blockIdx.x == 0 && blockIdx.y == 0) {
        if (tid < 128) { g_dsum[tid] = 0.0; g_dsq[tid] = 0.0; }
        if (tid == 0) g_ticket = 0;
    }

    int wm = warp >> 1;           // 0..7  -> 32-row slab
    int wn = warp & 1;            // 0..1  -> 64-col slab
    int m0 = blockIdx.x * GM_MT;

    int qr = lane >> 2;           // 0..7
    int qc = lane & 3;            // 0..3

    // ---- load full A tile (256 x 128) ----
#pragma unroll
    for (int it = 0; it < 16; it++) {
        int i = it * 512 + tid;
        int row = i >> 5;
        int col = (i & 31) * 4;
        int gm = m0 + row;
        float4 v = make_float4(0.f, 0.f, 0.f, 0.f);
        if (gm < M) v = *(const float4*)(A + (long long)gm * 128 + col);
        if (affine) {
            float4 sc = *(const float4*)(g_scale + col);
            float4 sh = *(const float4*)(g_shift + col);
            v.x = fmaf(v.x, sc.x, sh.x); v.x = v.x > 0.f ? v.x : v.x * SLOPE;
            v.y = fmaf(v.y, sc.y, sh.y); v.y = v.y > 0.f ? v.y : v.y * SLOPE;
            v.z = fmaf(v.z, sc.z, sh.z); v.z = v.z > 0.f ? v.z : v.z * SLOPE;
            v.w = fmaf(v.w, sc.w, sh.w); v.w = v.w > 0.f ? v.w : v.w * SLOPE;
        }
        unsigned* dst = As + row * GM_AS_STRIDE + col;
        dst[0] = f2tf(v.x); dst[1] = f2tf(v.y); dst[2] = f2tf(v.z); dst[3] = f2tf(v.w);
    }
    // ---- load full W (128 x 128) ----
#pragma unroll
    for (int it = 0; it < 8; it++) {
        int i = it * 512 + tid;
        int row = i >> 5;
        int col = (i & 31) * 4;
        float4 w = *(const float4*)(W + row * 128 + col);
        unsigned* dst = Ws + row * GM_AS_STRIDE + col;
        dst[0] = f2tf(w.x); dst[1] = f2tf(w.y); dst[2] = f2tf(w.z); dst[3] = f2tf(w.w);
    }
    __syncthreads();

    float acc[2][8][4];
#pragma unroll
    for (int i = 0; i < 2; i++)
#pragma unroll
        for (int j = 0; j < 8; j++)
#pragma unroll
            for (int k = 0; k < 4; k++) acc[i][j][k] = 0.f;

#pragma unroll
    for (int ks = 0; ks < 16; ks++) {
        int kb = ks * 8;
        unsigned a[2][4];
#pragma unroll
        for (int mi = 0; mi < 2; mi++) {
            int rb = wm * 32 + mi * 16 + qr;
            const unsigned* ap = As + rb * GM_AS_STRIDE + kb + qc;
            a[mi][0] = ap[0];
            a[mi][1] = ap[8 * GM_AS_STRIDE];
            a[mi][2] = ap[4];
            a[mi][3] = ap[8 * GM_AS_STRIDE + 4];
        }
#pragma unroll
        for (int ni = 0; ni < 8; ni++) {
            int n = wn * 64 + ni * 8 + qr;
            unsigned b0 = Ws[(kb + qc) * GM_AS_STRIDE + n];
            unsigned b1 = Ws[(kb + qc + 4) * GM_AS_STRIDE + n];
#pragma unroll
            for (int mi = 0; mi < 2; mi++) {
                asm volatile(
                    "mma.sync.aligned.m16n8k8.row.col.f32.tf32.tf32.f32 "
                    "{%0,%1,%2,%3}, {%4,%5,%6,%7}, {%8,%9}, {%0,%1,%2,%3};\n"
                    : "+f"(acc[mi][ni][0]), "+f"(acc[mi][ni][1]),
                      "+f"(acc[mi][ni][2]), "+f"(acc[mi][ni][3])
                    : "r"(a[mi][0]), "r"(a[mi][1]), "r"(a[mi][2]), "r"(a[mi][3]),
                      "r"(b0), "r"(b1));
            }
        }
    }

    // epilogue
#pragma unroll
    for (int mi = 0; mi < 2; mi++) {
        int r0 = m0 + wm * 32 + mi * 16 + qr;
#pragma unroll
        for (int ni = 0; ni < 8; ni++) {
            int col = wn * 64 + ni * 8 + qc * 2;
            float bx = 0.f, by = 0.f;
            if (bvec) { bx = bvec[col]; by = bvec[col + 1]; }
            if (r0 < M) {
                float2 o; o.x = acc[mi][ni][0] + bx; o.y = acc[mi][ni][1] + by;
                *(float2*)(C + (long long)r0 * 128 + col) = o;
            }
            if (r0 + 8 < M) {
                float2 o; o.x = acc[mi][ni][2] + bx; o.y = acc[mi][ni][3] + by;
                *(float2*)(C + (long long)(r0 + 8) * 128 + col) = o;
            }
        }
    }
}

// ---------------- fused GATv2 edge pass + BN statistics + BN finalize ----------------
// Softmax WITHOUT running max: scores are bounded (|e| < ~10 for this model;
// clamped at 80 => exp <= 5.5e34, fp32-safe). Mathematically identical to
// max-subtracted softmax; removes the loop-carried rescale chain and one MUFU.
// Pooled scheduling: warp g processes nodes g, g+W, g+2W, ... (pools degree
// variance over ~10 nodes -> minimal max-warp inflation per block).
__device__ __forceinline__ float gat_score(float4 ml, float4 xr4, float4 a4) {
    float px = ml.x + xr4.x; px = px > 0.f ? px : px * SLOPE;
    float py = ml.y + xr4.y; py = py > 0.f ? py : py * SLOPE;
    float pz = ml.z + xr4.z; pz = pz > 0.f ? pz : pz * SLOPE;
    float pw = ml.w + xr4.w; pw = pw > 0.f ? pw : pw * SLOPE;
    return px * a4.x + py * a4.y + pz * a4.z + pw * a4.w;
}

__global__ void __launch_bounds__(GAT_THREADS)
k_gat_bn(const float* __restrict__ xl, const float* __restrict__ xr,
         const float* __restrict__ xres, const float* __restrict__ att,
         const float* __restrict__ bias,
         const float* __restrict__ gamma, const float* __restrict__ beta,
         float* __restrict__ h, int N) {
    __shared__ float s_sum[128];
    __shared__ float s_sq[128];
    __shared__ int s_last;

    int tid = threadIdx.x;
    if (tid < 128) { s_sum[tid] = 0.f; s_sq[tid] = 0.f; }
    __syncthreads();

    int gwarp = blockIdx.x * (GAT_THREADS / 32) + (tid >> 5);
    int lane = tid & 31;

    float4 a4 = *(const float4*)(att + lane * 4);
    float4 b4 = *(const float4*)(bias + lane * 4);

    float lsum[4] = {0.f, 0.f, 0.f, 0.f};
    float lsq[4]  = {0.f, 0.f, 0.f, 0.f};

    for (int node = gwarp; node < N; node += GAT_WARPS) {
        float4 xr4 = *(const float4*)(xr + (long long)node * D + lane * 4);
        int beg = g_rowptr[node];
        int end = g_rowptr[node + 1];

        float s = 0.f;
        float4 acc = make_float4(0.f, 0.f, 0.f, 0.f);

        int e = beg;
        for (; e + 4 <= end; e += 4) {
            int si[4];
#pragma unroll
            for (int j = 0; j < 4; j++) si[j] = g_col[e + j];
            float4 ml[4];
#pragma unroll
            for (int j = 0; j < 4; j++)
                ml[j] = *(const float4*)(xl + (long long)si[j] * D + lane * 4);
            float pt[4];
#pragma unroll
            for (int j = 0; j < 4; j++) pt[j] = gat_score(ml[j], xr4, a4);
#pragma unroll
            for (int j = 0; j < 4; j++) pt[j] += __shfl_xor_sync(0xffffffffu, pt[j], 1);
#pragma unroll
            for (int j = 0; j < 4; j++) pt[j] += __shfl_xor_sync(0xffffffffu, pt[j], 2);
#pragma unroll
            for (int j = 0; j < 4; j++) pt[j] += __shfl_xor_sync(0xffffffffu, pt[j], 4);
            float p[4];
#pragma unroll
            for (int j = 0; j < 4; j++) p[j] = __expf(fminf(pt[j], 80.f));
#pragma unroll
            for (int j = 0; j < 4; j++) {
                s += p[j];
                acc.x = fmaf(p[j], ml[j].x, acc.x);
                acc.y = fmaf(p[j], ml[j].y, acc.y);
                acc.z = fmaf(p[j], ml[j].z, acc.z);
                acc.w = fmaf(p[j], ml[j].w, acc.w);
            }
        }
        for (; e < end; e++) {
            int s0 = g_col[e];
            float4 ml0 = *(const float4*)(xl + (long long)s0 * D + lane * 4);
            float pt = gat_score(ml0, xr4, a4);
            pt += __shfl_xor_sync(0xffffffffu, pt, 1);
            pt += __shfl_xor_sync(0xffffffffu, pt, 2);
            pt += __shfl_xor_sync(0xffffffffu, pt, 4);
            float p = __expf(fminf(pt, 80.f));
            s += p;
            acc.x = fmaf(p, ml0.x, acc.x);
            acc.y = fmaf(p, ml0.y, acc.y);
            acc.z = fmaf(p, ml0.z, acc.z);
            acc.w = fmaf(p, ml0.w, acc.w);
        }

        float inv = 1.f / s;  // self loop guarantees s >= exp(clamped score) > 0
        float4 r4 = *(const float4*)(xres + (long long)node * D + lane * 4);
        float4 o;
        o.x = acc.x * inv + b4.x + r4.x;
        o.y = acc.y * inv + b4.y + r4.y;
        o.z = acc.z * inv + b4.z + r4.z;
        o.w = acc.w * inv + b4.w + r4.w;
        *(float4*)(h + (long long)node * D + lane * 4) = o;

        // accumulate BN partials in registers (per warp-lane, channel-exclusive)
        lsum[0] += o.x; lsq[0] += o.x * o.x;
        lsum[1] += o.y; lsq[1] += o.y * o.y;
        lsum[2] += o.z; lsq[2] += o.z * o.z;
        lsum[3] += o.w; lsq[3] += o.w * o.w;
    }

    // fold per-warp register partials into block smem (channels lane-exclusive)
    int c = lane * 4;
#pragma unroll
    for (int j = 0; j < 4; j++) {
        atomicAdd(&s_sum[c + j], lsum[j]);
        atomicAdd(&s_sq[c + j],  lsq[j]);
    }
    __syncthreads();

    if (tid < 128) {
        atomicAdd(&g_dsum[tid], (double)s_sum[tid]);
        atomicAdd(&g_dsq[tid],  (double)s_sq[tid]);
    }
    __threadfence();
    __syncthreads();
    if (tid == 0) {
        int t = atomicAdd(&g_ticket, 1);
        s_last = (t == (int)gridDim.x - 1) ? 1 : 0;
    }
    __syncthreads();

    if (s_last && tid < 128) {
        double mean = __ldcg(&g_dsum[tid]) / (double)N;
        double var  = __ldcg(&g_dsq[tid]) / (double)N - mean * mean;
        float inv = rsqrtf((float)var + BN_EPS);
        float sc = gamma[tid] * inv;
        g_scale[tid] = sc;
        g_shift[tid] = beta[tid] - (float)mean * sc;
    }
}

// ---------------- launch ----------------
extern "C" void kernel_launch(void* const* d_in, const int* in_sizes, int n_in,
                              void* d_out, int out_size) {
    const float* x     = (const float*)d_in[0];
    const void*  ei    = d_in[1];
    const float* Wl    = (const float*)d_in[2];
    const float* Wr    = (const float*)d_in[3];
    const float* att   = (const float*)d_in[4];
    const float* bias  = (const float*)d_in[5];
    const float* Wres  = (const float*)d_in[6];
    const float* gamma = (const float*)d_in[7];
    const float* beta  = (const float*)d_in[8];
    const float* Wout  = (const float*)d_in[9];
    const float* bout  = (const float*)d_in[10];
    int N = in_sizes[0] / D;
    int E = in_sizes[1] / 2;
    float* out = (float*)d_out;

    float *p_xl, *p_xr, *p_xres, *p_h;
    cudaGetSymbolAddress((void**)&p_xl, g_xl);
    cudaGetSymbolAddress((void**)&p_xr, g_xr);
    cudaGetSymbolAddress((void**)&p_xres, g_xres);
    cudaGetSymbolAddress((void**)&p_h, g_h);

    static cudaStream_t s2 = []() {
        cudaStream_t s; cudaStreamCreateWithFlags(&s, cudaStreamNonBlocking); return s;
    }();
    static cudaEvent_t ev_fork = []() {
        cudaEvent_t e; cudaEventCreateWithFlags(&e, cudaEventDisableTiming); return e;
    }();
    static cudaEvent_t ev_csr = []() {
        cudaEvent_t e; cudaEventCreateWithFlags(&e, cudaEventDisableTiming); return e;
    }();
    static bool attr_ok = []() {
        cudaFuncSetAttribute(k_gemm3, cudaFuncAttributeMaxDynamicSharedMemorySize,
                             GM_SMEM_BYTES);
        return true;
    }();
    (void)attr_ok;

    int Et = E + N;
    int nb = (N + 1023) / 1024;

    int mtiles = (N + GM_MT - 1) / GM_MT;
    dim3 g3(mtiles, 3);
    dim3 g1(mtiles, 1);

    // fork: CSR build on s2, overlapped with layer-0 GEMM on the main stream
    cudaEventRecord(ev_fork, 0);
    k_gemm3<<<g3, 512, GM_SMEM_BYTES>>>(x, Wl, Wr, Wres,
                                        p_xl, p_xr, p_xres, nullptr, N, 0);
    cudaStreamWaitEvent(s2, ev_fork, 0);
    k_count<<<(Et + 255) / 256, 256, 0, s2>>>(ei, E, N);
    k_scan1<<<nb, 1024, 0, s2>>>(N);
    k_scan3<<<nb, 1024, 0, s2>>>(N);
    k_scatter<<<(Et + 255) / 256, 256, 0, s2>>>(ei, E, N);
    cudaEventRecord(ev_csr, s2);
    cudaStreamWaitEvent(0, ev_csr, 0);  // join CSR before first edge pass

    const float* xin = x;
    for (int l = 0; l < 3; l++) {
        if (l > 0) {
            k_gemm3<<<g3, 512, GM_SMEM_BYTES>>>(xin,
                                                Wl + l * D * D, Wr + l * D * D,
                                                Wres + l * D * D,
                                                p_xl, p_xr, p_xres, nullptr, N, 1);
        }
        k_gat_bn<<<GAT_BLOCKS, GAT_THREADS>>>(p_xl, p_xr, p_xres, att + l * D,
                                              bias + l * D, gamma + l * D,
                                              beta + l * D, p_h, N);
        xin = p_h;
    }
    k_gemm3<<<g1, 512, GM_SMEM_BYTES>>>(p_h, Wout, Wout, Wout, out, out, out, bout, N, 1);
}

// round 8
// speedup vs baseline: 2.4647x; 1.0002x over previous
#include <cuda_runtime.h>
#include <cuda_fp16.h>
#include <math.h>

#define D 128
#define SLOPE 0.2f
#define BN_EPS 1e-5f
#define MAXN 50048
#define MAXET 901120

// GEMM tile config: 256-row M tile, full K=128 resident in smem
#define GM_MT 256
#define GM_AS_STRIDE 132
#define GM_SMEM_BYTES ((GM_MT * GM_AS_STRIDE + 128 * GM_AS_STRIDE) * 4)

// GAT kernel launch shape: pooled strided warp scheduling
#define GAT_BLOCKS 592
#define GAT_THREADS 256
#define GAT_WARPS (GAT_BLOCKS * (GAT_THREADS / 32))

// ---------------- scratch (static device globals: allocation-free) ----------------
__device__ __align__(16) __half g_xl_h[MAXN * D];   // fp16 source-transform (gathered)
__device__ __align__(16) float g_xr[MAXN * D];
__device__ __align__(16) float g_xres[MAXN * D];
__device__ __align__(16) float g_h[MAXN * D];
__device__ int g_deg[MAXN];
__device__ int g_cursor[MAXN];
__device__ int g_rowptr[MAXN + 1];
__device__ int g_col[MAXET];
__device__ int g_bsum[64];
__device__ double g_dsum[D];
__device__ double g_dsq[D];
__device__ __align__(16) float g_scale[D];
__device__ __align__(16) float g_shift[D];
__device__ int g_ticket;

// int64-vs-int32 probe: odd 32-bit words of the first 8 values all zero => int64.
__device__ __forceinline__ int probe_is64(const unsigned int* __restrict__ p) {
    unsigned int o = 0;
#pragma unroll
    for (int j = 1; j < 16; j += 2) o |= p[j];
    return o == 0u;
}

// ---------------- CSR build ----------------
__global__ void k_count(const void* __restrict__ ei, int E, int N) {
    __shared__ int s64;
    if (threadIdx.x == 0) s64 = probe_is64((const unsigned int*)ei);
    __syncthreads();
    int is64 = s64;
    int t = blockIdx.x * blockDim.x + threadIdx.x;
    int Et = E + N;
    if (t >= Et) return;
    int d;
    if (t < E) {
        d = is64 ? (int)((const long long*)ei)[(long long)E + t]
                 : ((const int*)ei)[E + t];
    } else {
        d = t - E;  // self loop
    }
    atomicAdd(&g_deg[d], 1);
}

__global__ void k_scan1(int N) {
    __shared__ int s[1024];
    int tid = threadIdx.x;
    int i = blockIdx.x * 1024 + tid;
    int v = (i < N) ? g_deg[i] : 0;
    if (i < N) { g_deg[i] = 0; g_cursor[i] = 0; }  // restore zeros for next call
    s[tid] = v;
    __syncthreads();
    for (int off = 1; off < 1024; off <<= 1) {
        int t = 0;
        if (tid >= off) t = s[tid - off];
        __syncthreads();
        if (tid >= off) s[tid] += t;
        __syncthreads();
    }
    if (i < N) g_rowptr[i + 1] = s[tid];
    if (tid == 1023) g_bsum[blockIdx.x] = s[1023];
}

__global__ void k_scan3(int N) {
    __shared__ int sbase;
    if (threadIdx.x == 0) {
        int acc = 0;
        for (int b = 0; b < blockIdx.x; b++) acc += g_bsum[b];
        sbase = acc;
    }
    __syncthreads();
    int i = blockIdx.x * 1024 + threadIdx.x;
    if (i < N) g_rowptr[i + 1] += sbase;
    if (i == 0) g_rowptr[0] = 0;
}

__global__ void k_scatter(const void* __restrict__ ei, int E, int N) {
    __shared__ int s64;
    if (threadIdx.x == 0) s64 = probe_is64((const unsigned int*)ei);
    __syncthreads();
    int is64 = s64;
    int t = blockIdx.x * blockDim.x + threadIdx.x;
    int Et = E + N;
    if (t >= Et) return;
    int s, d;
    if (t < E) {
        if (is64) {
            s = (int)((const long long*)ei)[t];
            d = (int)((const long long*)ei)[(long long)E + t];
        } else {
            s = ((const int*)ei)[t];
            d = ((const int*)ei)[E + t];
        }
    } else {
        s = d = t - E;
    }
    int pos = g_rowptr[d] + atomicAdd(&g_cursor[d], 1);
    g_col[pos] = s;
}

// ---------------- tf32 tensor-core GEMM (whole-K, single sync) ----------------
// C[M,128] = act(A)[M,128] @ W[128,128] (+bias)
// Block: 512 threads (16 warps, 8x2), C tile 256x128, warp tile 32x64.
// y-slice 0 writes fp16 when c0half!=0 (xl buffer for the gather pass).
__device__ __forceinline__ unsigned f2tf(float x) {
    unsigned r;
    asm("cvt.rna.tf32.f32 %0, %1;" : "=r"(r) : "f"(x));
    return r;
}

__global__ void __launch_bounds__(512, 1)
k_gemm3(const float* __restrict__ A,
        const float* __restrict__ W0, const float* __restrict__ W1,
        const float* __restrict__ W2,
        void* __restrict__ C0v, float* __restrict__ C1, float* __restrict__ C2,
        const float* __restrict__ bvec, int M, int affine, int c0half) {
    const float* W = (blockIdx.y == 0) ? W0 : (blockIdx.y == 1 ? W1 : W2);
    float* C = (blockIdx.y == 0) ? (float*)C0v : (blockIdx.y == 1 ? C1 : C2);
    int ishalf = (blockIdx.y == 0) ? c0half : 0;

    extern __shared__ unsigned smem_u[];
    unsigned* As = smem_u;                            // [256][132]
    unsigned* Ws = smem_u + GM_MT * GM_AS_STRIDE;     // [128][132]

    int tid = threadIdx.x;
    int warp = tid >> 5;
    int lane = tid & 31;

    // zero BN accumulators for the following fused GAT+BN kernel
    if (blockIdx.x == 0 && blockIdx.y == 0) {
        if (tid < 128) { g_dsum[tid] = 0.0; g_dsq[tid] = 0.0; }
        if (tid == 0) g_ticket = 0;
    }

    int wm = warp >> 1;           // 0..7  -> 32-row slab
    int wn = warp & 1;            // 0..1  -> 64-col slab
    int m0 = blockIdx.x * GM_MT;

    int qr = lane >> 2;           // 0..7
    int qc = lane & 3;            // 0..3

    // ---- load full A tile (256 x 128) ----
#pragma unroll
    for (int it = 0; it < 16; it++) {
        int i = it * 512 + tid;
        int row = i >> 5;
        int col = (i & 31) * 4;
        int gm = m0 + row;
        float4 v = make_float4(0.f, 0.f, 0.f, 0.f);
        if (gm < M) v = *(const float4*)(A + (long long)gm * 128 + col);
        if (affine) {
            float4 sc = *(const float4*)(g_scale + col);
            float4 sh = *(const float4*)(g_shift + col);
            v.x = fmaf(v.x, sc.x, sh.x); v.x = v.x > 0.f ? v.x : v.x * SLOPE;
            v.y = fmaf(v.y, sc.y, sh.y); v.y = v.y > 0.f ? v.y : v.y * SLOPE;
            v.z = fmaf(v.z, sc.z, sh.z); v.z = v.z > 0.f ? v.z : v.z * SLOPE;
            v.w = fmaf(v.w, sc.w, sh.w); v.w = v.w > 0.f ? v.w : v.w * SLOPE;
        }
        unsigned* dst = As + row * GM_AS_STRIDE + col;
        dst[0] = f2tf(v.x); dst[1] = f2tf(v.y); dst[2] = f2tf(v.z); dst[3] = f2tf(v.w);
    }
    // ---- load full W (128 x 128) ----
#pragma unroll
    for (int it = 0; it < 8; it++) {
        int i = it * 512 + tid;
        int row = i >> 5;
        int col = (i & 31) * 4;
        float4 w = *(const float4*)(W + row * 128 + col);
        unsigned* dst = Ws + row * GM_AS_STRIDE + col;
        dst[0] = f2tf(w.x); dst[1] = f2tf(w.y); dst[2] = f2tf(w.z); dst[3] = f2tf(w.w);
    }
    __syncthreads();

    float acc[2][8][4];
#pragma unroll
    for (int i = 0; i < 2; i++)
#pragma unroll
        for (int j = 0; j < 8; j++)
#pragma unroll
            for (int k = 0; k < 4; k++) acc[i][j][k] = 0.f;

#pragma unroll
    for (int ks = 0; ks < 16; ks++) {
        int kb = ks * 8;
        unsigned a[2][4];
#pragma unroll
        for (int mi = 0; mi < 2; mi++) {
            int rb = wm * 32 + mi * 16 + qr;
            const unsigned* ap = As + rb * GM_AS_STRIDE + kb + qc;
            a[mi][0] = ap[0];
            a[mi][1] = ap[8 * GM_AS_STRIDE];
            a[mi][2] = ap[4];
            a[mi][3] = ap[8 * GM_AS_STRIDE + 4];
        }
#pragma unroll
        for (int ni = 0; ni < 8; ni++) {
            int n = wn * 64 + ni * 8 + qr;
            unsigned b0 = Ws[(kb + qc) * GM_AS_STRIDE + n];
            unsigned b1 = Ws[(kb + qc + 4) * GM_AS_STRIDE + n];
#pragma unroll
            for (int mi = 0; mi < 2; mi++) {
                asm volatile(
                    "mma.sync.aligned.m16n8k8.row.col.f32.tf32.tf32.f32 "
                    "{%0,%1,%2,%3}, {%4,%5,%6,%7}, {%8,%9}, {%0,%1,%2,%3};\n"
                    : "+f"(acc[mi][ni][0]), "+f"(acc[mi][ni][1]),
                      "+f"(acc[mi][ni][2]), "+f"(acc[mi][ni][3])
                    : "r"(a[mi][0]), "r"(a[mi][1]), "r"(a[mi][2]), "r"(a[mi][3]),
                      "r"(b0), "r"(b1));
            }
        }
    }

    // epilogue
    __half* Ch = (__half*)C0v;
#pragma unroll
    for (int mi = 0; mi < 2; mi++) {
        int r0 = m0 + wm * 32 + mi * 16 + qr;
#pragma unroll
        for (int ni = 0; ni < 8; ni++) {
            int col = wn * 64 + ni * 8 + qc * 2;
            float bx = 0.f, by = 0.f;
            if (bvec) { bx = bvec[col]; by = bvec[col + 1]; }
            if (ishalf) {
                if (r0 < M) {
                    __half2 o = __floats2half2_rn(acc[mi][ni][0] + bx, acc[mi][ni][1] + by);
                    *(__half2*)(Ch + (long long)r0 * 128 + col) = o;
                }
                if (r0 + 8 < M) {
                    __half2 o = __floats2half2_rn(acc[mi][ni][2] + bx, acc[mi][ni][3] + by);
                    *(__half2*)(Ch + (long long)(r0 + 8) * 128 + col) = o;
                }
            } else {
                if (r0 < M) {
                    float2 o; o.x = acc[mi][ni][0] + bx; o.y = acc[mi][ni][1] + by;
                    *(float2*)(C + (long long)r0 * 128 + col) = o;
                }
                if (r0 + 8 < M) {
                    float2 o; o.x = acc[mi][ni][2] + bx; o.y = acc[mi][ni][3] + by;
                    *(float2*)(C + (long long)(r0 + 8) * 128 + col) = o;
                }
            }
        }
    }
}

// ---------------- fused GATv2 edge pass + BN statistics + BN finalize ----------------
// xl gathered as fp16 (half the L2 gather traffic: 256B/warp/edge).
// Softmax without running max (scores bounded; clamp at 80 for overflow safety).
__device__ __forceinline__ float4 ld_xl_h(const __half* __restrict__ xlh,
                                          long long node, int lane) {
    uint2 raw = *(const uint2*)(xlh + node * D + lane * 4);
    __half2 h01 = *(__half2*)&raw.x;
    __half2 h23 = *(__half2*)&raw.y;
    float2 f01 = __half22float2(h01);
    float2 f23 = __half22float2(h23);
    return make_float4(f01.x, f01.y, f23.x, f23.y);
}

__device__ __forceinline__ float gat_score(float4 ml, float4 xr4, float4 a4) {
    float px = ml.x + xr4.x; px = px > 0.f ? px : px * SLOPE;
    float py = ml.y + xr4.y; py = py > 0.f ? py : py * SLOPE;
    float pz = ml.z + xr4.z; pz = pz > 0.f ? pz : pz * SLOPE;
    float pw = ml.w + xr4.w; pw = pw > 0.f ? pw : pw * SLOPE;
    return px * a4.x + py * a4.y + pz * a4.z + pw * a4.w;
}

__global__ void __launch_bounds__(GAT_THREADS)
k_gat_bn(const __half* __restrict__ xl, const float* __restrict__ xr,
         const float* __restrict__ xres, const float* __restrict__ att,
         const float* __restrict__ bias,
         const float* __restrict__ gamma, const float* __restrict__ beta,
         float* __restrict__ h, int N) {
    __shared__ float s_sum[128];
    __shared__ float s_sq[128];
    __shared__ int s_last;

    int tid = threadIdx.x;
    if (tid < 128) { s_sum[tid] = 0.f; s_sq[tid] = 0.f; }
    __syncthreads();

    int gwarp = blockIdx.x * (GAT_THREADS / 32) + (tid >> 5);
    int lane = tid & 31;

    float4 a4 = *(const float4*)(att + lane * 4);
    float4 b4 = *(const float4*)(bias + lane * 4);

    float lsum[4] = {0.f, 0.f, 0.f, 0.f};
    float lsq[4]  = {0.f, 0.f, 0.f, 0.f};

    for (int node = gwarp; node < N; node += GAT_WARPS) {
        float4 xr4 = *(const float4*)(xr + (long long)node * D + lane * 4);
        int beg = g_rowptr[node];
        int end = g_rowptr[node + 1];

        float s = 0.f;
        float4 acc = make_float4(0.f, 0.f, 0.f, 0.f);

        int e = beg;
        for (; e + 4 <= end; e += 4) {
            int si[4];
#pragma unroll
            for (int j = 0; j < 4; j++) si[j] = g_col[e + j];
            float4 ml[4];
#pragma unroll
            for (int j = 0; j < 4; j++) ml[j] = ld_xl_h(xl, si[j], lane);
            float pt[4];
#pragma unroll
            for (int j = 0; j < 4; j++) pt[j] = gat_score(ml[j], xr4, a4);
#pragma unroll
            for (int j = 0; j < 4; j++) pt[j] += __shfl_xor_sync(0xffffffffu, pt[j], 1);
#pragma unroll
            for (int j = 0; j < 4; j++) pt[j] += __shfl_xor_sync(0xffffffffu, pt[j], 2);
#pragma unroll
            for (int j = 0; j < 4; j++) pt[j] += __shfl_xor_sync(0xffffffffu, pt[j], 4);
            float p[4];
#pragma unroll
            for (int j = 0; j < 4; j++) p[j] = __expf(fminf(pt[j], 80.f));
#pragma unroll
            for (int j = 0; j < 4; j++) {
                s += p[j];
                acc.x = fmaf(p[j], ml[j].x, acc.x);
                acc.y = fmaf(p[j], ml[j].y, acc.y);
                acc.z = fmaf(p[j], ml[j].z, acc.z);
                acc.w = fmaf(p[j], ml[j].w, acc.w);
            }
        }
        for (; e < end; e++) {
            int s0 = g_col[e];
            float4 ml0 = ld_xl_h(xl, s0, lane);
            float pt = gat_score(ml0, xr4, a4);
            pt += __shfl_xor_sync(0xffffffffu, pt, 1);
            pt += __shfl_xor_sync(0xffffffffu, pt, 2);
            pt += __shfl_xor_sync(0xffffffffu, pt, 4);
            float p = __expf(fminf(pt, 80.f));
            s += p;
            acc.x = fmaf(p, ml0.x, acc.x);
            acc.y = fmaf(p, ml0.y, acc.y);
            acc.z = fmaf(p, ml0.z, acc.z);
            acc.w = fmaf(p, ml0.w, acc.w);
        }

        float inv = 1.f / s;
        float4 r4 = *(const float4*)(xres + (long long)node * D + lane * 4);
        float4 o;
        o.x = acc.x * inv + b4.x + r4.x;
        o.y = acc.y * inv + b4.y + r4.y;
        o.z = acc.z * inv + b4.z + r4.z;
        o.w = acc.w * inv + b4.w + r4.w;
        *(float4*)(h + (long long)node * D + lane * 4) = o;

        lsum[0] += o.x; lsq[0] += o.x * o.x;
        lsum[1] += o.y; lsq[1] += o.y * o.y;
        lsum[2] += o.z; lsq[2] += o.z * o.z;
        lsum[3] += o.w; lsq[3] += o.w * o.w;
    }

    int c = lane * 4;
#pragma unroll
    for (int j = 0; j < 4; j++) {
        atomicAdd(&s_sum[c + j], lsum[j]);
        atomicAdd(&s_sq[c + j],  lsq[j]);
    }
    __syncthreads();

    if (tid < 128) {
        atomicAdd(&g_dsum[tid], (double)s_sum[tid]);
        atomicAdd(&g_dsq[tid],  (double)s_sq[tid]);
    }
    __threadfence();
    __syncthreads();
    if (tid == 0) {
        int t = atomicAdd(&g_ticket, 1);
        s_last = (t == (int)gridDim.x - 1) ? 1 : 0;
    }
    __syncthreads();

    if (s_last && tid < 128) {
        double mean = __ldcg(&g_dsum[tid]) / (double)N;
        double var  = __ldcg(&g_dsq[tid]) / (double)N - mean * mean;
        float inv = rsqrtf((float)var + BN_EPS);
        float sc = gamma[tid] * inv;
        g_scale[tid] = sc;
        g_shift[tid] = beta[tid] - (float)mean * sc;
    }
}

// ---------------- launch ----------------
extern "C" void kernel_launch(void* const* d_in, const int* in_sizes, int n_in,
                              void* d_out, int out_size) {
    const float* x     = (const float*)d_in[0];
    const void*  ei    = d_in[1];
    const float* Wl    = (const float*)d_in[2];
    const float* Wr    = (const float*)d_in[3];
    const float* att   = (const float*)d_in[4];
    const float* bias  = (const float*)d_in[5];
    const float* Wres  = (const float*)d_in[6];
    const float* gamma = (const float*)d_in[7];
    const float* beta  = (const float*)d_in[8];
    const float* Wout  = (const float*)d_in[9];
    const float* bout  = (const float*)d_in[10];
    int N = in_sizes[0] / D;
    int E = in_sizes[1] / 2;
    float* out = (float*)d_out;

    __half* p_xlh;
    float *p_xr, *p_xres, *p_h;
    cudaGetSymbolAddress((void**)&p_xlh, g_xl_h);
    cudaGetSymbolAddress((void**)&p_xr, g_xr);
    cudaGetSymbolAddress((void**)&p_xres, g_xres);
    cudaGetSymbolAddress((void**)&p_h, g_h);

    static cudaStream_t s2 = []() {
        cudaStream_t s; cudaStreamCreateWithFlags(&s, cudaStreamNonBlocking); return s;
    }();
    static cudaEvent_t ev_fork = []() {
        cudaEvent_t e; cudaEventCreateWithFlags(&e, cudaEventDisableTiming); return e;
    }();
    static cudaEvent_t ev_csr = []() {
        cudaEvent_t e; cudaEventCreateWithFlags(&e, cudaEventDisableTiming); return e;
    }();
    static bool attr_ok = []() {
        cudaFuncSetAttribute(k_gemm3, cudaFuncAttributeMaxDynamicSharedMemorySize,
                             GM_SMEM_BYTES);
        return true;
    }();
    (void)attr_ok;

    int Et = E + N;
    int nb = (N + 1023) / 1024;

    int mtiles = (N + GM_MT - 1) / GM_MT;
    dim3 g3(mtiles, 3);
    dim3 g1(mtiles, 1);

    // fork: CSR build on s2, overlapped with layer-0 GEMM on the main stream
    cudaEventRecord(ev_fork, 0);
    k_gemm3<<<g3, 512, GM_SMEM_BYTES>>>(x, Wl, Wr, Wres,
                                        p_xlh, p_xr, p_xres, nullptr, N, 0, 1);
    cudaStreamWaitEvent(s2, ev_fork, 0);
    k_count<<<(Et + 255) / 256, 256, 0, s2>>>(ei, E, N);
    k_scan1<<<nb, 1024, 0, s2>>>(N);
    k_scan3<<<nb, 1024, 0, s2>>>(N);
    k_scatter<<<(Et + 255) / 256, 256, 0, s2>>>(ei, E, N);
    cudaEventRecord(ev_csr, s2);
    cudaStreamWaitEvent(0, ev_csr, 0);  // join CSR before first edge pass

    const float* xin = x;
    for (int l = 0; l < 3; l++) {
        if (l > 0) {
            k_gemm3<<<g3, 512, GM_SMEM_BYTES>>>(xin,
                                                Wl + l * D * D, Wr + l * D * D,
                                                Wres + l * D * D,
                                                p_xlh, p_xr, p_xres, nullptr, N, 1, 1);
        }
        k_gat_bn<<<GAT_BLOCKS, GAT_THREADS>>>(p_xlh, p_xr, p_xres, att + l * D,
                                              bias + l * D, gamma + l * D,
                                              beta + l * D, p_h, N);
        xin = p_h;
    }
    k_gemm3<<<g1, 512, GM_SMEM_BYTES>>>(p_h, Wout, Wout, Wout,
                                        out, out, out, bout, N, 1, 0);
}